// round 1
// baseline (speedup 1.0000x reference)
#include <cuda_runtime.h>
#include <cuda_bf16.h>

// Problem dims
constexpr int Bb = 4, Tt = 2048, Cc = 1024, Hh = 16, Dd = 64;
constexpr int MROWS = Bb * Tt;      // 8192
constexpr int HD    = Hh * Dd;      // 1024

// Scratch (device globals — no runtime allocation allowed)
__device__ float g_Wqt[Cc * HD];
__device__ float g_Wkt[Cc * HD];
__device__ float g_Wvt[Cc * HD];
__device__ float g_Q [MROWS * HD];
__device__ float g_K [MROWS * HD];
__device__ float g_V [MROWS * HD];
__device__ float g_AO[MROWS * HD];

// ---------------------------------------------------------------------------
// Pack weights: Wq/Wk/Wv [H, C, D] -> [C, H*D] (GEMM B-matrix, row-major K x N)
// ---------------------------------------------------------------------------
__global__ void pack_w_kernel(const float* __restrict__ Wq,
                              const float* __restrict__ Wk,
                              const float* __restrict__ Wv) {
    int idx = blockIdx.x * 256 + threadIdx.x;   // over C*HD = 1M, exact
    int c = idx >> 10;
    int j = idx & 1023;
    int src = (j >> 6) * (Cc * Dd) + c * Dd + (j & 63);
    g_Wqt[idx] = Wq[src];
    g_Wkt[idx] = Wk[src];
    g_Wvt[idx] = Wv[src];
}

// ---------------------------------------------------------------------------
// SGEMM: C[M,N] = A[M,K] * B[K,N] (+ bias[N]); all row-major.
// BM=BN=128, BK=8, 256 threads, 8x8 per thread. M,N,K multiples of 128/8.
// ---------------------------------------------------------------------------
__global__ __launch_bounds__(256) void sgemm128(
    const float* __restrict__ A, const float* __restrict__ B,
    float* __restrict__ C, int M, int N, int K,
    const float* __restrict__ bias) {
    __shared__ float As[8 * 132];   // transposed A tile, padded (528B rows, 16B aligned)
    __shared__ float Bs[8 * 128];

    const int tid = threadIdx.x;
    const int tx = tid & 15, ty = tid >> 4;
    const int bn = blockIdx.x, bm = blockIdx.y;

    const int arow = tid >> 1, ak = (tid & 1) * 4;
    const int bk = tid >> 5, bc = (tid & 31) * 4;

    const float* Ap = A + (bm * 128 + arow) * K + ak;
    const float* Bp = B + bk * N + bn * 128 + bc;

    float acc[8][8];
#pragma unroll
    for (int i = 0; i < 8; i++)
#pragma unroll
        for (int j = 0; j < 8; j++) acc[i][j] = 0.f;

    for (int k0 = 0; k0 < K; k0 += 8) {
        float4 a = *(const float4*)Ap; Ap += 8;
        float4 b = *(const float4*)Bp; Bp += 8 * N;
        As[(ak + 0) * 132 + arow] = a.x;
        As[(ak + 1) * 132 + arow] = a.y;
        As[(ak + 2) * 132 + arow] = a.z;
        As[(ak + 3) * 132 + arow] = a.w;
        *(float4*)&Bs[bk * 128 + bc] = b;
        __syncthreads();
#pragma unroll
        for (int kk = 0; kk < 8; kk++) {
            float4 a0 = *(const float4*)&As[kk * 132 + ty * 8];
            float4 a1 = *(const float4*)&As[kk * 132 + ty * 8 + 4];
            float4 b0 = *(const float4*)&Bs[kk * 128 + tx * 8];
            float4 b1 = *(const float4*)&Bs[kk * 128 + tx * 8 + 4];
            float ar[8] = {a0.x, a0.y, a0.z, a0.w, a1.x, a1.y, a1.z, a1.w};
            float br[8] = {b0.x, b0.y, b0.z, b0.w, b1.x, b1.y, b1.z, b1.w};
#pragma unroll
            for (int i = 0; i < 8; i++)
#pragma unroll
                for (int j = 0; j < 8; j++) acc[i][j] += ar[i] * br[j];
        }
        __syncthreads();
    }

    float bb[8];
#pragma unroll
    for (int j = 0; j < 8; j++)
        bb[j] = bias ? bias[bn * 128 + tx * 8 + j] : 0.f;

#pragma unroll
    for (int i = 0; i < 8; i++) {
        int row = bm * 128 + ty * 8 + i;
        float4 o0, o1;
        o0.x = acc[i][0] + bb[0]; o0.y = acc[i][1] + bb[1];
        o0.z = acc[i][2] + bb[2]; o0.w = acc[i][3] + bb[3];
        o1.x = acc[i][4] + bb[4]; o1.y = acc[i][5] + bb[5];
        o1.z = acc[i][6] + bb[6]; o1.w = acc[i][7] + bb[7];
        *(float4*)&C[row * N + bn * 128 + tx * 8]     = o0;
        *(float4*)&C[row * N + bn * 128 + tx * 8 + 4] = o1;
    }
}

// ---------------------------------------------------------------------------
// Causal flash attention, fp32. Per block: one (b, h, qtile of 64 rows).
// BQ=BK=64, D=64, 256 threads, 4x4 microtiles. Q/K/V layout: [B*T, H*D].
// ---------------------------------------------------------------------------
constexpr int FLASH_SMEM_FLOATS = 4 * 64 * 65 + 64 * 16 + 3 * 64;  // 17856
constexpr int FLASH_SMEM_BYTES  = FLASH_SMEM_FLOATS * 4;           // 71424

__global__ __launch_bounds__(256) void flash_kernel(
    const float* __restrict__ Q, const float* __restrict__ K,
    const float* __restrict__ V, float* __restrict__ O) {
    extern __shared__ float sm[];
    float* Qs  = sm;                 // [64][65]
    float* Ks  = Qs + 64 * 65;       // [64][65]
    float* Vs  = Ks + 64 * 65;       // [64][65]
    float* Ps  = Vs + 64 * 65;       // [64][65]
    float* red = Ps + 64 * 65;       // [64][16]
    float* m_s = red + 64 * 16;      // [64]
    float* l_s = m_s + 64;           // [64]
    float* f_s = l_s + 64;           // [64]

    const int qt = blockIdx.x, h = blockIdx.y, b = blockIdx.z;
    const int tid = threadIdx.x;
    const int tx = tid & 15, ty = tid >> 4;

    // Load Q tile
    const int qbase = (b * Tt + qt * 64) * HD + h * Dd;
#pragma unroll
    for (int i = 0; i < 4; i++) {
        int e = tid + i * 256;
        int row = e >> 4, cv = (e & 15) * 4;
        float4 v4 = *(const float4*)&Q[qbase + row * HD + cv];
        Qs[row * 65 + cv + 0] = v4.x;
        Qs[row * 65 + cv + 1] = v4.y;
        Qs[row * 65 + cv + 2] = v4.z;
        Qs[row * 65 + cv + 3] = v4.w;
    }
    if (tid < 64) { m_s[tid] = -3.0e38f; l_s[tid] = 0.f; }

    float o[4][4];
#pragma unroll
    for (int i = 0; i < 4; i++)
#pragma unroll
        for (int j = 0; j < 4; j++) o[i][j] = 0.f;
    __syncthreads();

    for (int kt = 0; kt <= qt; kt++) {
        const int kbase = (b * Tt + kt * 64) * HD + h * Dd;
#pragma unroll
        for (int i = 0; i < 4; i++) {
            int e = tid + i * 256;
            int row = e >> 4, cv = (e & 15) * 4;
            float4 kv = *(const float4*)&K[kbase + row * HD + cv];
            Ks[row * 65 + cv + 0] = kv.x;
            Ks[row * 65 + cv + 1] = kv.y;
            Ks[row * 65 + cv + 2] = kv.z;
            Ks[row * 65 + cv + 3] = kv.w;
            float4 vv = *(const float4*)&V[kbase + row * HD + cv];
            Vs[row * 65 + cv + 0] = vv.x;
            Vs[row * 65 + cv + 1] = vv.y;
            Vs[row * 65 + cv + 2] = vv.z;
            Vs[row * 65 + cv + 3] = vv.w;
        }
        __syncthreads();

        // S = (Q K^T) * scale
        float s[4][4];
#pragma unroll
        for (int i = 0; i < 4; i++)
#pragma unroll
            for (int j = 0; j < 4; j++) s[i][j] = 0.f;
#pragma unroll 8
        for (int k = 0; k < 64; k++) {
            float qa[4], kb[4];
#pragma unroll
            for (int i = 0; i < 4; i++) qa[i] = Qs[(ty * 4 + i) * 65 + k];
#pragma unroll
            for (int j = 0; j < 4; j++) kb[j] = Ks[(tx * 4 + j) * 65 + k];
#pragma unroll
            for (int i = 0; i < 4; i++)
#pragma unroll
                for (int j = 0; j < 4; j++) s[i][j] += qa[i] * kb[j];
        }
#pragma unroll
        for (int i = 0; i < 4; i++)
#pragma unroll
            for (int j = 0; j < 4; j++) s[i][j] *= 0.03125f;  // 1/sqrt(1024)
        if (kt == qt) {
#pragma unroll
            for (int i = 0; i < 4; i++)
#pragma unroll
                for (int j = 0; j < 4; j++)
                    if (tx * 4 + j > ty * 4 + i) s[i][j] = -3.0e38f;
        }

        // Row max (partials -> smem -> 64-thread finish)
#pragma unroll
        for (int i = 0; i < 4; i++) {
            float rm = fmaxf(fmaxf(s[i][0], s[i][1]), fmaxf(s[i][2], s[i][3]));
            red[(ty * 4 + i) * 16 + tx] = rm;
        }
        __syncthreads();
        if (tid < 64) {
            float mx = red[tid * 16];
#pragma unroll
            for (int g = 1; g < 16; g++) mx = fmaxf(mx, red[tid * 16 + g]);
            float mo = m_s[tid];
            float mn = fmaxf(mo, mx);
            float f = __expf(mo - mn);
            m_s[tid] = mn; f_s[tid] = f; l_s[tid] *= f;
        }
        __syncthreads();

        // P = exp(S - m); partial row sums; rescale O
        float rs[4];
#pragma unroll
        for (int i = 0; i < 4; i++) {
            float mi = m_s[ty * 4 + i];
            rs[i] = 0.f;
#pragma unroll
            for (int j = 0; j < 4; j++) {
                float p = __expf(s[i][j] - mi);
                Ps[(ty * 4 + i) * 65 + tx * 4 + j] = p;
                rs[i] += p;
            }
        }
#pragma unroll
        for (int i = 0; i < 4; i++) red[(ty * 4 + i) * 16 + tx] = rs[i];
#pragma unroll
        for (int i = 0; i < 4; i++) {
            float f = f_s[ty * 4 + i];
#pragma unroll
            for (int j = 0; j < 4; j++) o[i][j] *= f;
        }
        __syncthreads();
        if (tid < 64) {
            float ssum = 0.f;
#pragma unroll
            for (int g = 0; g < 16; g++) ssum += red[tid * 16 + g];
            l_s[tid] += ssum;
        }

        // O += P @ V
#pragma unroll 8
        for (int sIdx = 0; sIdx < 64; sIdx++) {
            float pa[4], vb[4];
#pragma unroll
            for (int i = 0; i < 4; i++) pa[i] = Ps[(ty * 4 + i) * 65 + sIdx];
#pragma unroll
            for (int j = 0; j < 4; j++) vb[j] = Vs[sIdx * 65 + tx * 4 + j];
#pragma unroll
            for (int i = 0; i < 4; i++)
#pragma unroll
                for (int j = 0; j < 4; j++) o[i][j] += pa[i] * vb[j];
        }
        __syncthreads();
    }

    // Finalize: O /= l, write [B*T, H*D]
#pragma unroll
    for (int i = 0; i < 4; i++) {
        float inv = 1.0f / l_s[ty * 4 + i];
        float4 w;
        w.x = o[i][0] * inv; w.y = o[i][1] * inv;
        w.z = o[i][2] * inv; w.w = o[i][3] * inv;
        int row = b * Tt + qt * 64 + ty * 4 + i;
        *(float4*)&O[row * HD + h * Dd + tx * 4] = w;
    }
}

// ---------------------------------------------------------------------------
// Launch
// ---------------------------------------------------------------------------
extern "C" void kernel_launch(void* const* d_in, const int* in_sizes, int n_in,
                              void* d_out, int out_size) {
    const float* q  = (const float*)d_in[0];
    const float* k  = (const float*)d_in[1];
    const float* v  = (const float*)d_in[2];
    const float* Wq = (const float*)d_in[3];
    const float* Wk = (const float*)d_in[4];
    const float* Wv = (const float*)d_in[5];
    const float* Wo = (const float*)d_in[6];
    const float* bo = (const float*)d_in[7];
    float* out = (float*)d_out;

    void *pWqt, *pWkt, *pWvt, *pQ, *pK, *pV, *pAO;
    cudaGetSymbolAddress(&pWqt, g_Wqt);
    cudaGetSymbolAddress(&pWkt, g_Wkt);
    cudaGetSymbolAddress(&pWvt, g_Wvt);
    cudaGetSymbolAddress(&pQ,  g_Q);
    cudaGetSymbolAddress(&pK,  g_K);
    cudaGetSymbolAddress(&pV,  g_V);
    cudaGetSymbolAddress(&pAO, g_AO);

    pack_w_kernel<<<(Cc * HD) / 256, 256>>>(Wq, Wk, Wv);

    dim3 gg(HD / 128, MROWS / 128);  // (8, 64)
    sgemm128<<<gg, 256>>>(q, (const float*)pWqt, (float*)pQ, MROWS, HD, Cc, nullptr);
    sgemm128<<<gg, 256>>>(k, (const float*)pWkt, (float*)pK, MROWS, HD, Cc, nullptr);
    sgemm128<<<gg, 256>>>(v, (const float*)pWvt, (float*)pV, MROWS, HD, Cc, nullptr);

    cudaFuncSetAttribute(flash_kernel,
                         cudaFuncAttributeMaxDynamicSharedMemorySize,
                         FLASH_SMEM_BYTES);
    flash_kernel<<<dim3(Tt / 64, Hh, Bb), 256, FLASH_SMEM_BYTES>>>(
        (const float*)pQ, (const float*)pK, (const float*)pV, (float*)pAO);

    sgemm128<<<dim3(Cc / 128, MROWS / 128), 256>>>(
        (const float*)pAO, Wo, out, MROWS, Cc, HD, bo);
}

// round 3
// speedup vs baseline: 1.2313x; 1.2313x over previous
#include <cuda_runtime.h>
#include <cuda_bf16.h>
#include <cstdint>

// Problem dims
constexpr int Bb = 4, Tt = 2048, Cc = 1024, Hh = 16, Dd = 64;
constexpr int MROWS = Bb * Tt;      // 8192
constexpr int HD    = Hh * Dd;      // 1024

// Scratch (device globals — no runtime allocation allowed)
__device__ float g_Wqt[HD * Cc];    // [N=HD, K=C]  (B^T layout for MMA)
__device__ float g_Wkt[HD * Cc];
__device__ float g_Wvt[HD * Cc];
__device__ float g_Wot[Cc * HD];    // [N=C, K=HD]
__device__ float g_Q [MROWS * HD];
__device__ float g_K [MROWS * HD];
__device__ float g_V [MROWS * HD];
__device__ float g_AO[MROWS * HD];

// ---------------------------------------------------------------------------
// Helpers
// ---------------------------------------------------------------------------
__device__ __forceinline__ uint32_t smem_u32(const void* p) {
    uint32_t a;
    asm("{ .reg .u64 t; cvta.to.shared.u64 t, %1; cvt.u32.u64 %0, t; }"
        : "=r"(a) : "l"(p));
    return a;
}
__device__ __forceinline__ float tf32_rna(float x) {
    float r; asm("cvt.rna.tf32.f32 %0, %1;" : "=f"(r) : "f"(x)); return r;
}
__device__ __forceinline__ void ldsm_x4(uint32_t addr, uint32_t* d) {
    asm volatile("ldmatrix.sync.aligned.m8n8.x4.shared.b16 {%0,%1,%2,%3}, [%4];"
        : "=r"(d[0]), "=r"(d[1]), "=r"(d[2]), "=r"(d[3]) : "r"(addr));
}
__device__ __forceinline__ void ldsm_x2(uint32_t addr, uint32_t* d) {
    asm volatile("ldmatrix.sync.aligned.m8n8.x2.shared.b16 {%0,%1}, [%2];"
        : "=r"(d[0]), "=r"(d[1]) : "r"(addr));
}
__device__ __forceinline__ void mma_tf32(float* c, const uint32_t* a, const uint32_t* b) {
    asm volatile("mma.sync.aligned.m16n8k8.row.col.f32.tf32.tf32.f32 "
        "{%0,%1,%2,%3}, {%4,%5,%6,%7}, {%8,%9}, {%0,%1,%2,%3};"
        : "+f"(c[0]), "+f"(c[1]), "+f"(c[2]), "+f"(c[3])
        : "r"(a[0]), "r"(a[1]), "r"(a[2]), "r"(a[3]), "r"(b[0]), "r"(b[1]));
}

// ---------------------------------------------------------------------------
// Pack: Wq/Wk/Wv [H,C,D] -> [N=HD, K=C];  Wo [HD,C] -> [N=C, K=HD]
// ---------------------------------------------------------------------------
__global__ void pack_w_kernel(const float* __restrict__ Wq,
                              const float* __restrict__ Wk,
                              const float* __restrict__ Wv,
                              const float* __restrict__ Wo) {
    int idx = blockIdx.x * 256 + threadIdx.x;   // [0, HD*C)
    int n = idx >> 10;           // row of Bt (N index)
    int c = idx & 1023;          // col of Bt (K index)
    int src = (n >> 6) * (Cc * Dd) + c * Dd + (n & 63);
    g_Wqt[idx] = Wq[src];
    g_Wkt[idx] = Wk[src];
    g_Wvt[idx] = Wv[src];
    g_Wot[idx] = Wo[c * Cc + n];  // Wot[n][c] = Wo[c][n]  (HD == C == 1024)
}

// ---------------------------------------------------------------------------
// 3xTF32 mma.sync GEMM: C[M,N] = A[M,K] * Bt[N,K]^T (+bias). Row-major A, Bt.
// CTA 128x128x32, 256 thr (8 warps, 2x4), warp 64x32, m16n8k8 atoms 4x4.
// Double-buffered smem: per stage {Ahi, Alo, Bhi, Blo}[128][PITCH].
// ---------------------------------------------------------------------------
constexpr int PITCH = 36;                               // floats; 144B rows (16B aligned)
constexpr int ARR   = 128 * PITCH;                      // floats per array
constexpr int STAGE = 4 * ARR;                          // floats per stage
constexpr int GEMM_SMEM_BYTES = 2 * STAGE * 4;          // 147456

__global__ __launch_bounds__(256, 1) void gemm_mma(
    const float* __restrict__ A, const float* __restrict__ Bt,
    float* __restrict__ C, int M, int N, int K, const float* __restrict__ bias) {
    extern __shared__ float sm[];
    const uint32_t sbase = smem_u32(sm);
    const int tid  = threadIdx.x;
    const int lane = tid & 31, wid = tid >> 5;
    const int wm = wid >> 2, wn = wid & 3;     // warp tile origin (wm*64, wn*32)
    const int bn = blockIdx.x, bm = blockIdx.y;
    const int iters = K >> 5;

    // gmem loader mapping: thread covers row r, 16 floats at hf*16
    const int r = tid >> 1, hf = tid & 1;
    const float* Ap = A  + (size_t)(bm * 128 + r) * K + hf * 16;
    const float* Bp = Bt + (size_t)(bn * 128 + r) * K + hf * 16;

    float4 aR[4], bR[4];
#pragma unroll
    for (int i = 0; i < 4; i++) {
        aR[i] = *(const float4*)(Ap + i * 4);
        bR[i] = *(const float4*)(Bp + i * 4);
    }

    float acc[4][4][4];
#pragma unroll
    for (int ma = 0; ma < 4; ma++)
#pragma unroll
        for (int na = 0; na < 4; na++)
#pragma unroll
            for (int i = 0; i < 4; i++) acc[ma][na][i] = 0.f;

    const int stoff = r * PITCH + hf * 16;
    auto sts_tiles = [&](int st) {
        float* b0 = sm + st * STAGE;
#pragma unroll
        for (int i = 0; i < 4; i++) {
            float4 h, l;
            h.x = tf32_rna(aR[i].x); l.x = tf32_rna(aR[i].x - h.x);
            h.y = tf32_rna(aR[i].y); l.y = tf32_rna(aR[i].y - h.y);
            h.z = tf32_rna(aR[i].z); l.z = tf32_rna(aR[i].z - h.z);
            h.w = tf32_rna(aR[i].w); l.w = tf32_rna(aR[i].w - h.w);
            *(float4*)&b0[stoff + i * 4]       = h;
            *(float4*)&b0[ARR + stoff + i * 4] = l;
            h.x = tf32_rna(bR[i].x); l.x = tf32_rna(bR[i].x - h.x);
            h.y = tf32_rna(bR[i].y); l.y = tf32_rna(bR[i].y - h.y);
            h.z = tf32_rna(bR[i].z); l.z = tf32_rna(bR[i].z - h.z);
            h.w = tf32_rna(bR[i].w); l.w = tf32_rna(bR[i].w - h.w);
            *(float4*)&b0[2 * ARR + stoff + i * 4] = h;
            *(float4*)&b0[3 * ARR + stoff + i * 4] = l;
        }
    };

    sts_tiles(0);
    __syncthreads();

    // per-lane ldmatrix address components
    const int a_row = ((lane >> 3) & 1) * 8 + (lane & 7);   // within 16-row atom
    const int a_col = (lane >> 4) * 4;                      // tf32 col offset (0 or 4)
    const int b_row = lane & 7;                             // within 8-row n-atom
    const int b_col = ((lane >> 3) & 1) * 4;

#pragma unroll 1
    for (int it = 0; it < iters; ++it) {
        const int cur = it & 1;
        if (it + 1 < iters) {
            const float* Ap2 = Ap + (it + 1) * 32;
            const float* Bp2 = Bp + (it + 1) * 32;
#pragma unroll
            for (int i = 0; i < 4; i++) {
                aR[i] = *(const float4*)(Ap2 + i * 4);
                bR[i] = *(const float4*)(Bp2 + i * 4);
            }
        }

        const uint32_t stb = sbase + (uint32_t)(cur * STAGE) * 4u;
        const uint32_t aH = stb + (uint32_t)((wm * 64 + a_row) * PITCH + a_col) * 4u;
        const uint32_t aL = aH + ARR * 4u;
        const uint32_t bH = stb + 2u * ARR * 4u +
                            (uint32_t)((wn * 32 + b_row) * PITCH + b_col) * 4u;
        const uint32_t bL = bH + ARR * 4u;

#pragma unroll
        for (int ks = 0; ks < 4; ks++) {
            uint32_t ah[4][4], al[4][4], bh[4][2], bl[4][2];
#pragma unroll
            for (int ma = 0; ma < 4; ma++) {
                uint32_t off = (uint32_t)(ma * 16 * PITCH + ks * 8) * 4u;
                ldsm_x4(aH + off, ah[ma]);
                ldsm_x4(aL + off, al[ma]);
            }
#pragma unroll
            for (int na = 0; na < 4; na++) {
                uint32_t off = (uint32_t)(na * 8 * PITCH + ks * 8) * 4u;
                ldsm_x2(bH + off, bh[na]);
                ldsm_x2(bL + off, bl[na]);
            }
#pragma unroll
            for (int ma = 0; ma < 4; ma++)
#pragma unroll
                for (int na = 0; na < 4; na++) {
                    mma_tf32(acc[ma][na], ah[ma], bh[na]);
                    mma_tf32(acc[ma][na], ah[ma], bl[na]);
                    mma_tf32(acc[ma][na], al[ma], bh[na]);
                }
        }

        if (it + 1 < iters) {
            __syncthreads();          // all warps done reading buffer (it+1)&1 (from it-1)
            sts_tiles((it + 1) & 1);
            __syncthreads();
        }
    }

    // Epilogue: write accumulators (+bias) straight to gmem
    const int grp = lane >> 2, qid = lane & 3;
#pragma unroll
    for (int ma = 0; ma < 4; ma++) {
        const int row0 = bm * 128 + wm * 64 + ma * 16 + grp;
#pragma unroll
        for (int na = 0; na < 4; na++) {
            const int col = bn * 128 + wn * 32 + na * 8 + qid * 2;
            float bx = 0.f, by = 0.f;
            if (bias) { bx = bias[col]; by = bias[col + 1]; }
            float2 v0 = make_float2(acc[ma][na][0] + bx, acc[ma][na][1] + by);
            float2 v1 = make_float2(acc[ma][na][2] + bx, acc[ma][na][3] + by);
            *(float2*)&C[(size_t)row0 * N + col]       = v0;
            *(float2*)&C[(size_t)(row0 + 8) * N + col] = v1;
        }
    }
}

// ---------------------------------------------------------------------------
// Fast exp: e^x via 2^(x*log2e), FFMA-only (no MUFU). x <= 0 expected.
// ---------------------------------------------------------------------------
__device__ __forceinline__ float fast_exp(float x) {
    float y = x * 1.4426950408889634f;
    y = fmaxf(y, -126.0f);              // also catches the -3e38 mask values
    int ni = __float2int_rn(y);
    float r = y - (float)ni;            // r in [-0.5, 0.5]
    float p = fmaf(r, 0.0013333558f, 0.0096181290f);
    p = fmaf(r, p, 0.0555041087f);
    p = fmaf(r, p, 0.2402265070f);
    p = fmaf(r, p, 0.6931471806f);
    p = fmaf(r, p, 1.0f);
    return p * __int_as_float((ni + 127) << 23);
}

// ---------------------------------------------------------------------------
// Causal flash attention, fp32, BQ=BK=64, 256 threads, 4x4 microtiles.
// ---------------------------------------------------------------------------
constexpr int FLASH_SMEM_FLOATS = 4 * 64 * 65 + 64 * 16 + 3 * 64;
constexpr int FLASH_SMEM_BYTES  = FLASH_SMEM_FLOATS * 4;

__global__ __launch_bounds__(256) void flash_kernel(
    const float* __restrict__ Q, const float* __restrict__ K,
    const float* __restrict__ V, float* __restrict__ O) {
    extern __shared__ float sm[];
    float* Qs  = sm;
    float* Ks  = Qs + 64 * 65;
    float* Vs  = Ks + 64 * 65;
    float* Ps  = Vs + 64 * 65;
    float* red = Ps + 64 * 65;
    float* m_s = red + 64 * 16;
    float* l_s = m_s + 64;
    float* f_s = l_s + 64;

    const int qt = blockIdx.x, h = blockIdx.y, b = blockIdx.z;
    const int tid = threadIdx.x;
    const int tx = tid & 15, ty = tid >> 4;

    const int qbase = (b * Tt + qt * 64) * HD + h * Dd;
#pragma unroll
    for (int i = 0; i < 4; i++) {
        int e = tid + i * 256;
        int row = e >> 4, cv = (e & 15) * 4;
        float4 v4 = *(const float4*)&Q[qbase + row * HD + cv];
        Qs[row * 65 + cv + 0] = v4.x;
        Qs[row * 65 + cv + 1] = v4.y;
        Qs[row * 65 + cv + 2] = v4.z;
        Qs[row * 65 + cv + 3] = v4.w;
    }
    if (tid < 64) { m_s[tid] = -3.0e38f; l_s[tid] = 0.f; }

    float o[4][4];
#pragma unroll
    for (int i = 0; i < 4; i++)
#pragma unroll
        for (int j = 0; j < 4; j++) o[i][j] = 0.f;
    __syncthreads();

    for (int kt = 0; kt <= qt; kt++) {
        const int kbase = (b * Tt + kt * 64) * HD + h * Dd;
#pragma unroll
        for (int i = 0; i < 4; i++) {
            int e = tid + i * 256;
            int row = e >> 4, cv = (e & 15) * 4;
            float4 kv = *(const float4*)&K[kbase + row * HD + cv];
            Ks[row * 65 + cv + 0] = kv.x;
            Ks[row * 65 + cv + 1] = kv.y;
            Ks[row * 65 + cv + 2] = kv.z;
            Ks[row * 65 + cv + 3] = kv.w;
            float4 vv = *(const float4*)&V[kbase + row * HD + cv];
            Vs[row * 65 + cv + 0] = vv.x;
            Vs[row * 65 + cv + 1] = vv.y;
            Vs[row * 65 + cv + 2] = vv.z;
            Vs[row * 65 + cv + 3] = vv.w;
        }
        __syncthreads();

        float s[4][4];
#pragma unroll
        for (int i = 0; i < 4; i++)
#pragma unroll
            for (int j = 0; j < 4; j++) s[i][j] = 0.f;
#pragma unroll 8
        for (int k = 0; k < 64; k++) {
            float qa[4], kb[4];
#pragma unroll
            for (int i = 0; i < 4; i++) qa[i] = Qs[(ty * 4 + i) * 65 + k];
#pragma unroll
            for (int j = 0; j < 4; j++) kb[j] = Ks[(tx * 4 + j) * 65 + k];
#pragma unroll
            for (int i = 0; i < 4; i++)
#pragma unroll
                for (int j = 0; j < 4; j++) s[i][j] += qa[i] * kb[j];
        }
#pragma unroll
        for (int i = 0; i < 4; i++)
#pragma unroll
            for (int j = 0; j < 4; j++) s[i][j] *= 0.03125f;
        if (kt == qt) {
#pragma unroll
            for (int i = 0; i < 4; i++)
#pragma unroll
                for (int j = 0; j < 4; j++)
                    if (tx * 4 + j > ty * 4 + i) s[i][j] = -3.0e38f;
        }

#pragma unroll
        for (int i = 0; i < 4; i++) {
            float rm = fmaxf(fmaxf(s[i][0], s[i][1]), fmaxf(s[i][2], s[i][3]));
            red[(ty * 4 + i) * 16 + tx] = rm;
        }
        __syncthreads();
        if (tid < 64) {
            float mx = red[tid * 16];
#pragma unroll
            for (int g = 1; g < 16; g++) mx = fmaxf(mx, red[tid * 16 + g]);
            float mo = m_s[tid];
            float mn = fmaxf(mo, mx);
            float f = fast_exp(mo - mn);
            m_s[tid] = mn; f_s[tid] = f; l_s[tid] *= f;
        }
        __syncthreads();

        float rs[4];
#pragma unroll
        for (int i = 0; i < 4; i++) {
            float mi = m_s[ty * 4 + i];
            rs[i] = 0.f;
#pragma unroll
            for (int j = 0; j < 4; j++) {
                float p = fast_exp(s[i][j] - mi);
                Ps[(ty * 4 + i) * 65 + tx * 4 + j] = p;
                rs[i] += p;
            }
        }
#pragma unroll
        for (int i = 0; i < 4; i++) red[(ty * 4 + i) * 16 + tx] = rs[i];
#pragma unroll
        for (int i = 0; i < 4; i++) {
            float f = f_s[ty * 4 + i];
#pragma unroll
            for (int j = 0; j < 4; j++) o[i][j] *= f;
        }
        __syncthreads();
        if (tid < 64) {
            float ssum = 0.f;
#pragma unroll
            for (int g = 0; g < 16; g++) ssum += red[tid * 16 + g];
            l_s[tid] += ssum;
        }

#pragma unroll 8
        for (int sIdx = 0; sIdx < 64; sIdx++) {
            float pa[4], vb[4];
#pragma unroll
            for (int i = 0; i < 4; i++) pa[i] = Ps[(ty * 4 + i) * 65 + sIdx];
#pragma unroll
            for (int j = 0; j < 4; j++) vb[j] = Vs[sIdx * 65 + tx * 4 + j];
#pragma unroll
            for (int i = 0; i < 4; i++)
#pragma unroll
                for (int j = 0; j < 4; j++) o[i][j] += pa[i] * vb[j];
        }
        __syncthreads();
    }

#pragma unroll
    for (int i = 0; i < 4; i++) {
        float inv = 1.0f / l_s[ty * 4 + i];
        float4 w;
        w.x = o[i][0] * inv; w.y = o[i][1] * inv;
        w.z = o[i][2] * inv; w.w = o[i][3] * inv;
        int row = b * Tt + qt * 64 + ty * 4 + i;
        *(float4*)&O[row * HD + h * Dd + tx * 4] = w;
    }
}

// ---------------------------------------------------------------------------
// Launch
// ---------------------------------------------------------------------------
extern "C" void kernel_launch(void* const* d_in, const int* in_sizes, int n_in,
                              void* d_out, int out_size) {
    const float* q  = (const float*)d_in[0];
    const float* k  = (const float*)d_in[1];
    const float* v  = (const float*)d_in[2];
    const float* Wq = (const float*)d_in[3];
    const float* Wk = (const float*)d_in[4];
    const float* Wv = (const float*)d_in[5];
    const float* Wo = (const float*)d_in[6];
    const float* bo = (const float*)d_in[7];
    float* out = (float*)d_out;

    void *pWqt, *pWkt, *pWvt, *pWot, *pQ, *pK, *pV, *pAO;
    cudaGetSymbolAddress(&pWqt, g_Wqt);
    cudaGetSymbolAddress(&pWkt, g_Wkt);
    cudaGetSymbolAddress(&pWvt, g_Wvt);
    cudaGetSymbolAddress(&pWot, g_Wot);
    cudaGetSymbolAddress(&pQ,  g_Q);
    cudaGetSymbolAddress(&pK,  g_K);
    cudaGetSymbolAddress(&pV,  g_V);
    cudaGetSymbolAddress(&pAO, g_AO);

    cudaFuncSetAttribute(gemm_mma,
                         cudaFuncAttributeMaxDynamicSharedMemorySize, GEMM_SMEM_BYTES);
    cudaFuncSetAttribute(flash_kernel,
                         cudaFuncAttributeMaxDynamicSharedMemorySize, FLASH_SMEM_BYTES);

    pack_w_kernel<<<(Cc * HD) / 256, 256>>>(Wq, Wk, Wv, Wo);

    dim3 gg(HD / 128, MROWS / 128);  // (8, 64)
    gemm_mma<<<gg, 256, GEMM_SMEM_BYTES>>>(q, (const float*)pWqt, (float*)pQ,
                                           MROWS, HD, Cc, nullptr);
    gemm_mma<<<gg, 256, GEMM_SMEM_BYTES>>>(k, (const float*)pWkt, (float*)pK,
                                           MROWS, HD, Cc, nullptr);
    gemm_mma<<<gg, 256, GEMM_SMEM_BYTES>>>(v, (const float*)pWvt, (float*)pV,
                                           MROWS, HD, Cc, nullptr);

    flash_kernel<<<dim3(Tt / 64, Hh, Bb), 256, FLASH_SMEM_BYTES>>>(
        (const float*)pQ, (const float*)pK, (const float*)pV, (float*)pAO);

    gemm_mma<<<dim3(Cc / 128, MROWS / 128), 256, GEMM_SMEM_BYTES>>>(
        (const float*)pAO, (const float*)pWot, out, MROWS, Cc, HD, bo);
}

// round 4
// speedup vs baseline: 1.7437x; 1.4162x over previous
#include <cuda_runtime.h>
#include <cuda_bf16.h>
#include <cstdint>

// Problem dims
constexpr int Bb = 4, Tt = 2048, Cc = 1024, Hh = 16, Dd = 64;
constexpr int MROWS = Bb * Tt;      // 8192
constexpr int HD    = Hh * Dd;      // 1024

// Scratch (device globals — no runtime allocation allowed)
__device__ float g_Wqt[HD * Cc];    // [N=HD, K=C]
__device__ float g_Wkt[HD * Cc];
__device__ float g_Wvt[HD * Cc];
__device__ float g_Wot[Cc * HD];    // [N=C, K=HD]
__device__ __nv_bfloat16 g_Qh[MROWS * HD];
__device__ __nv_bfloat16 g_Ql[MROWS * HD];
__device__ __nv_bfloat16 g_Kh[MROWS * HD];
__device__ __nv_bfloat16 g_Kl[MROWS * HD];
__device__ __nv_bfloat16 g_Vh[MROWS * HD];
__device__ __nv_bfloat16 g_Vl[MROWS * HD];
__device__ float g_AO[MROWS * HD];

// ---------------------------------------------------------------------------
// Helpers
// ---------------------------------------------------------------------------
__device__ __forceinline__ uint32_t smem_u32(const void* p) {
    uint32_t a;
    asm("{ .reg .u64 t; cvta.to.shared.u64 t, %1; cvt.u32.u64 %0, t; }"
        : "=r"(a) : "l"(p));
    return a;
}
__device__ __forceinline__ float tf32_rna(float x) {
    float r; asm("cvt.rna.tf32.f32 %0, %1;" : "=f"(r) : "f"(x)); return r;
}
__device__ __forceinline__ void ldsm_x4(uint32_t addr, uint32_t* d) {
    asm volatile("ldmatrix.sync.aligned.m8n8.x4.shared.b16 {%0,%1,%2,%3}, [%4];"
        : "=r"(d[0]), "=r"(d[1]), "=r"(d[2]), "=r"(d[3]) : "r"(addr));
}
__device__ __forceinline__ void ldsm_x4_t(uint32_t addr, uint32_t* d) {
    asm volatile("ldmatrix.sync.aligned.m8n8.x4.trans.shared.b16 {%0,%1,%2,%3}, [%4];"
        : "=r"(d[0]), "=r"(d[1]), "=r"(d[2]), "=r"(d[3]) : "r"(addr));
}
__device__ __forceinline__ void ldsm_x2(uint32_t addr, uint32_t* d) {
    asm volatile("ldmatrix.sync.aligned.m8n8.x2.shared.b16 {%0,%1}, [%2];"
        : "=r"(d[0]), "=r"(d[1]) : "r"(addr));
}
__device__ __forceinline__ void mma_tf32(float* c, const uint32_t* a, const uint32_t* b) {
    asm volatile("mma.sync.aligned.m16n8k8.row.col.f32.tf32.tf32.f32 "
        "{%0,%1,%2,%3}, {%4,%5,%6,%7}, {%8,%9}, {%0,%1,%2,%3};"
        : "+f"(c[0]), "+f"(c[1]), "+f"(c[2]), "+f"(c[3])
        : "r"(a[0]), "r"(a[1]), "r"(a[2]), "r"(a[3]), "r"(b[0]), "r"(b[1]));
}
__device__ __forceinline__ void mma_bf16(float* c, const uint32_t* a,
                                         uint32_t b0, uint32_t b1) {
    asm volatile("mma.sync.aligned.m16n8k16.row.col.f32.bf16.bf16.f32 "
        "{%0,%1,%2,%3}, {%4,%5,%6,%7}, {%8,%9}, {%0,%1,%2,%3};"
        : "+f"(c[0]), "+f"(c[1]), "+f"(c[2]), "+f"(c[3])
        : "r"(a[0]), "r"(a[1]), "r"(a[2]), "r"(a[3]), "r"(b0), "r"(b1));
}
__device__ __forceinline__ void cpa16(uint32_t dst, const void* src) {
    asm volatile("cp.async.cg.shared.global [%0], [%1], 16;" :: "r"(dst), "l"(src));
}
#define CP_COMMIT() asm volatile("cp.async.commit_group;" ::: "memory")
#define CP_WAIT0()  asm volatile("cp.async.wait_group 0;" ::: "memory")
#define CP_WAIT1()  asm volatile("cp.async.wait_group 1;" ::: "memory")

// 2^z via FFMA-only poly (z <= ~0 expected; clamps handle -inf masks)
__device__ __forceinline__ float fast_exp2(float z) {
    z = fmaxf(z, -126.0f);
    float ni = rintf(z);
    float r = z - ni;
    float p = fmaf(r, 0.0013333558f, 0.0096181290f);
    p = fmaf(r, p, 0.0555041087f);
    p = fmaf(r, p, 0.2402265070f);
    p = fmaf(r, p, 0.6931471806f);
    p = fmaf(r, p, 1.0f);
    return p * __int_as_float(((int)ni + 127) << 23);
}

// ---------------------------------------------------------------------------
// Pack: Wq/Wk/Wv [H,C,D] -> [N=HD, K=C];  Wo [HD,C] -> [N=C, K=HD]
// ---------------------------------------------------------------------------
__global__ void pack_w_kernel(const float* __restrict__ Wq,
                              const float* __restrict__ Wk,
                              const float* __restrict__ Wv,
                              const float* __restrict__ Wo) {
    int idx = blockIdx.x * 256 + threadIdx.x;
    int n = idx >> 10;
    int c = idx & 1023;
    int src = (n >> 6) * (Cc * Dd) + c * Dd + (n & 63);
    g_Wqt[idx] = Wq[src];
    g_Wkt[idx] = Wk[src];
    g_Wvt[idx] = Wv[src];
    g_Wot[idx] = Wo[c * Cc + n];
}

// ---------------------------------------------------------------------------
// 3xTF32 mma.sync GEMM. C=A*Bt^T. If Ch!=null, write bf16 hi/lo split arrays
// instead of fp32 C. CTA 128x128x32, 8 warps, warp 64x32.
// ---------------------------------------------------------------------------
constexpr int PITCH = 36;
constexpr int ARR   = 128 * PITCH;
constexpr int STAGE = 4 * ARR;
constexpr int GEMM_SMEM_BYTES = 2 * STAGE * 4;

__global__ __launch_bounds__(256, 1) void gemm_mma(
    const float* __restrict__ A, const float* __restrict__ Bt,
    float* __restrict__ C, __nv_bfloat16* __restrict__ Ch,
    __nv_bfloat16* __restrict__ Cl,
    int M, int N, int K, const float* __restrict__ bias) {
    extern __shared__ float sm[];
    const uint32_t sbase = smem_u32(sm);
    const int tid  = threadIdx.x;
    const int lane = tid & 31, wid = tid >> 5;
    const int wm = wid >> 2, wn = wid & 3;
    const int bn = blockIdx.x, bm = blockIdx.y;
    const int iters = K >> 5;

    const int r = tid >> 1, hf = tid & 1;
    const float* Ap = A  + (size_t)(bm * 128 + r) * K + hf * 16;
    const float* Bp = Bt + (size_t)(bn * 128 + r) * K + hf * 16;

    float4 aR[4], bR[4];
#pragma unroll
    for (int i = 0; i < 4; i++) {
        aR[i] = *(const float4*)(Ap + i * 4);
        bR[i] = *(const float4*)(Bp + i * 4);
    }

    float acc[4][4][4];
#pragma unroll
    for (int ma = 0; ma < 4; ma++)
#pragma unroll
        for (int na = 0; na < 4; na++)
#pragma unroll
            for (int i = 0; i < 4; i++) acc[ma][na][i] = 0.f;

    const int stoff = r * PITCH + hf * 16;
    auto sts_tiles = [&](int st) {
        float* b0 = sm + st * STAGE;
#pragma unroll
        for (int i = 0; i < 4; i++) {
            float4 h, l;
            h.x = tf32_rna(aR[i].x); l.x = tf32_rna(aR[i].x - h.x);
            h.y = tf32_rna(aR[i].y); l.y = tf32_rna(aR[i].y - h.y);
            h.z = tf32_rna(aR[i].z); l.z = tf32_rna(aR[i].z - h.z);
            h.w = tf32_rna(aR[i].w); l.w = tf32_rna(aR[i].w - h.w);
            *(float4*)&b0[stoff + i * 4]       = h;
            *(float4*)&b0[ARR + stoff + i * 4] = l;
            h.x = tf32_rna(bR[i].x); l.x = tf32_rna(bR[i].x - h.x);
            h.y = tf32_rna(bR[i].y); l.y = tf32_rna(bR[i].y - h.y);
            h.z = tf32_rna(bR[i].z); l.z = tf32_rna(bR[i].z - h.z);
            h.w = tf32_rna(bR[i].w); l.w = tf32_rna(bR[i].w - h.w);
            *(float4*)&b0[2 * ARR + stoff + i * 4] = h;
            *(float4*)&b0[3 * ARR + stoff + i * 4] = l;
        }
    };

    sts_tiles(0);
    __syncthreads();

    const int a_row = lane & 15;
    const int a_col = (lane >> 4) * 4;
    const int b_row = lane & 7;
    const int b_col = ((lane >> 3) & 1) * 4;

#pragma unroll 1
    for (int it = 0; it < iters; ++it) {
        const int cur = it & 1;
        if (it + 1 < iters) {
            const float* Ap2 = Ap + (it + 1) * 32;
            const float* Bp2 = Bp + (it + 1) * 32;
#pragma unroll
            for (int i = 0; i < 4; i++) {
                aR[i] = *(const float4*)(Ap2 + i * 4);
                bR[i] = *(const float4*)(Bp2 + i * 4);
            }
        }

        const uint32_t stb = sbase + (uint32_t)(cur * STAGE) * 4u;
        const uint32_t aH = stb + (uint32_t)((wm * 64 + a_row) * PITCH + a_col) * 4u;
        const uint32_t aL = aH + ARR * 4u;
        const uint32_t bH = stb + 2u * ARR * 4u +
                            (uint32_t)((wn * 32 + b_row) * PITCH + b_col) * 4u;
        const uint32_t bL = bH + ARR * 4u;

#pragma unroll
        for (int ks = 0; ks < 4; ks++) {
            uint32_t ah[4][4], al[4][4], bh[4][2], bl[4][2];
#pragma unroll
            for (int ma = 0; ma < 4; ma++) {
                uint32_t off = (uint32_t)(ma * 16 * PITCH + ks * 8) * 4u;
                ldsm_x4(aH + off, ah[ma]);
                ldsm_x4(aL + off, al[ma]);
            }
#pragma unroll
            for (int na = 0; na < 4; na++) {
                uint32_t off = (uint32_t)(na * 8 * PITCH + ks * 8) * 4u;
                ldsm_x2(bH + off, bh[na]);
                ldsm_x2(bL + off, bl[na]);
            }
#pragma unroll
            for (int ma = 0; ma < 4; ma++)
#pragma unroll
                for (int na = 0; na < 4; na++) {
                    mma_tf32(acc[ma][na], ah[ma], bh[na]);
                    mma_tf32(acc[ma][na], ah[ma], bl[na]);
                    mma_tf32(acc[ma][na], al[ma], bh[na]);
                }
        }

        if (it + 1 < iters) {
            __syncthreads();
            sts_tiles((it + 1) & 1);
            __syncthreads();
        }
    }

    const int grp = lane >> 2, qid = lane & 3;
#pragma unroll
    for (int ma = 0; ma < 4; ma++) {
        const int row0 = bm * 128 + wm * 64 + ma * 16 + grp;
#pragma unroll
        for (int na = 0; na < 4; na++) {
            const int col = bn * 128 + wn * 32 + na * 8 + qid * 2;
            if (Ch) {
                // bf16 hi/lo split output
#pragma unroll
                for (int half = 0; half < 2; half++) {
                    float x = acc[ma][na][half * 2 + 0];
                    float y = acc[ma][na][half * 2 + 1];
                    __nv_bfloat162 hp = __float22bfloat162_rn(make_float2(x, y));
                    float2 hf2 = __bfloat1622float2(hp);
                    __nv_bfloat162 lp =
                        __float22bfloat162_rn(make_float2(x - hf2.x, y - hf2.y));
                    size_t off = (size_t)(row0 + half * 8) * N + col;
                    *reinterpret_cast<__nv_bfloat162*>(&Ch[off]) = hp;
                    *reinterpret_cast<__nv_bfloat162*>(&Cl[off]) = lp;
                }
            } else {
                float bx = 0.f, by = 0.f;
                if (bias) { bx = bias[col]; by = bias[col + 1]; }
                float2 v0 = make_float2(acc[ma][na][0] + bx, acc[ma][na][1] + by);
                float2 v1 = make_float2(acc[ma][na][2] + bx, acc[ma][na][3] + by);
                *(float2*)&C[(size_t)row0 * N + col]       = v0;
                *(float2*)&C[(size_t)(row0 + 8) * N + col] = v1;
            }
        }
    }
}

// ---------------------------------------------------------------------------
// Tensor-core causal flash attention, 3xBF16.
// CTA: 128 thr (4 warps), BQ=64 (warp = m16), BK=64, D=64.
// smem: Qh,Ql + 2 stages x {Kh,Kl,Vh,Vl}; tiles [64][72] bf16 (144B pitch).
// ---------------------------------------------------------------------------
constexpr int FP = 72;                       // bf16 pitch (144 bytes)
constexpr int TILE_B = 64 * FP * 2;          // 9216 bytes per array
constexpr int F_QH = 0, F_QL = TILE_B;
constexpr int F_ST0 = 2 * TILE_B;            // stage stride = 4*TILE_B
constexpr int FLASH2_SMEM = (2 + 8) * TILE_B;  // 92160

__global__ __launch_bounds__(128) void flash2_kernel() {
    extern __shared__ char fsm[];
    const uint32_t sb = smem_u32(fsm);
    const int tid = threadIdx.x;
    const int lane = tid & 31, wm = tid >> 5;
    const int qt = blockIdx.x, h = blockIdx.y, b = blockIdx.z;

    const size_t qrow = (size_t)(b * Tt + qt * 64) * HD + h * 64;

    // --- async tile copy: 64 rows x 128B, thread covers row tid>>1, 64B half
    const int crow = tid >> 1, cseg = tid & 1;
    auto copy_tile = [&](uint32_t soff, const __nv_bfloat16* g) {
        const char* gp = (const char*)(g) + (size_t)crow * (HD * 2) + cseg * 64;
        uint32_t sp = sb + soff + crow * 144 + cseg * 64;
#pragma unroll
        for (int i = 0; i < 4; i++) cpa16(sp + i * 16, gp + i * 16);
    };

    copy_tile(F_QH, g_Qh + qrow);
    copy_tile(F_QL, g_Ql + qrow);
    {
        const size_t krow = (size_t)(b * Tt) * HD + h * 64;
        copy_tile(F_ST0 + 0 * TILE_B, g_Kh + krow);
        copy_tile(F_ST0 + 1 * TILE_B, g_Kl + krow);
        copy_tile(F_ST0 + 2 * TILE_B, g_Vh + krow);
        copy_tile(F_ST0 + 3 * TILE_B, g_Vl + krow);
    }
    CP_COMMIT();
    CP_WAIT0();
    __syncthreads();

    // --- hoist Q fragments (A-operand, m16 rows wm*16..+15)
    uint32_t qh[4][4], ql[4][4];
    {
        const uint32_t qa = sb + (uint32_t)((wm * 16 + (lane & 15)) * 144 +
                                            (lane >> 4) * 16);
#pragma unroll
        for (int ks = 0; ks < 4; ks++) {
            ldsm_x4(F_QH + qa + ks * 32, qh[ks]);
            ldsm_x4(F_QL + qa + ks * 32, ql[ks]);
        }
    }

    float oacc[8][4];
#pragma unroll
    for (int na = 0; na < 8; na++)
#pragma unroll
        for (int i = 0; i < 4; i++) oacc[na][i] = 0.f;
    float mrow[2] = {-3.0e38f, -3.0e38f};
    float lrow[2] = {0.f, 0.f};

    constexpr float SC = 0.045084971874737f;   // (1/32) * log2(e)

    // ldsm address components
    const uint32_t kadd = (uint32_t)(((lane & 7) + (lane >> 4) * 8) * 144 +
                                     ((lane >> 3) & 1) * 16);
    const uint32_t vadd = (uint32_t)(((lane & 7) + ((lane >> 3) & 1) * 8) * 144 +
                                     (lane >> 4) * 16);
    const int grp = lane >> 2, qid = lane & 3;

#pragma unroll 1
    for (int kt = 0; kt <= qt; kt++) {
        const uint32_t stg = sb + F_ST0 + (uint32_t)((kt & 1) * 4 * TILE_B);

        if (kt < qt) {
            const size_t krow = (size_t)(b * Tt + (kt + 1) * 64) * HD + h * 64;
            const uint32_t nst = F_ST0 + (uint32_t)(((kt + 1) & 1) * 4 * TILE_B);
            copy_tile(nst + 0 * TILE_B, g_Kh + krow);
            copy_tile(nst + 1 * TILE_B, g_Kl + krow);
            copy_tile(nst + 2 * TILE_B, g_Vh + krow);
            copy_tile(nst + 3 * TILE_B, g_Vl + krow);
            CP_COMMIT();
            CP_WAIT1();
        } else {
            CP_WAIT0();
        }
        __syncthreads();

        // ---- S = Q K^T (3xBF16)
        float sacc[8][4];
#pragma unroll
        for (int na = 0; na < 8; na++)
#pragma unroll
            for (int i = 0; i < 4; i++) sacc[na][i] = 0.f;

#pragma unroll
        for (int ks = 0; ks < 4; ks++) {
#pragma unroll
            for (int pr = 0; pr < 4; pr++) {
                uint32_t kfh[4], kfl[4];
                const uint32_t ka = stg + (uint32_t)(pr * 16 * 144 + ks * 32) + kadd;
                ldsm_x4(ka, kfh);                        // Kh
                ldsm_x4(ka + TILE_B, kfl);               // Kl
                mma_bf16(sacc[2 * pr],     qh[ks], kfh[0], kfh[1]);
                mma_bf16(sacc[2 * pr + 1], qh[ks], kfh[2], kfh[3]);
                mma_bf16(sacc[2 * pr],     qh[ks], kfl[0], kfl[1]);
                mma_bf16(sacc[2 * pr + 1], qh[ks], kfl[2], kfl[3]);
                mma_bf16(sacc[2 * pr],     ql[ks], kfh[0], kfh[1]);
                mma_bf16(sacc[2 * pr + 1], ql[ks], kfh[2], kfh[3]);
            }
        }

        // ---- causal mask on diagonal tile
        if (kt == qt) {
            const int r0 = wm * 16 + grp;
#pragma unroll
            for (int na = 0; na < 8; na++) {
                const int c0 = na * 8 + qid * 2;
                if (c0 > r0)     sacc[na][0] = -3.0e38f;
                if (c0 + 1 > r0) sacc[na][1] = -3.0e38f;
                if (c0 > r0 + 8)     sacc[na][2] = -3.0e38f;
                if (c0 + 1 > r0 + 8) sacc[na][3] = -3.0e38f;
            }
        }

        // ---- online softmax (raw-S units; scale folded into exp2 arg)
        float rmax[2];
        rmax[0] = sacc[0][0]; rmax[1] = sacc[0][2];
#pragma unroll
        for (int na = 0; na < 8; na++) {
            rmax[0] = fmaxf(rmax[0], fmaxf(sacc[na][0], sacc[na][1]));
            rmax[1] = fmaxf(rmax[1], fmaxf(sacc[na][2], sacc[na][3]));
        }
#pragma unroll
        for (int d = 1; d <= 2; d <<= 1) {
            rmax[0] = fmaxf(rmax[0], __shfl_xor_sync(0xffffffffu, rmax[0], d));
            rmax[1] = fmaxf(rmax[1], __shfl_xor_sync(0xffffffffu, rmax[1], d));
        }
        float mnew[2], fsc[2];
#pragma unroll
        for (int i = 0; i < 2; i++) {
            mnew[i] = fmaxf(mrow[i], rmax[i]);
            fsc[i] = fast_exp2((mrow[i] - mnew[i]) * SC);
            mrow[i] = mnew[i];
        }

        float rsum[2] = {0.f, 0.f};
#pragma unroll
        for (int na = 0; na < 8; na++) {
            sacc[na][0] = fast_exp2((sacc[na][0] - mnew[0]) * SC);
            sacc[na][1] = fast_exp2((sacc[na][1] - mnew[0]) * SC);
            sacc[na][2] = fast_exp2((sacc[na][2] - mnew[1]) * SC);
            sacc[na][3] = fast_exp2((sacc[na][3] - mnew[1]) * SC);
            rsum[0] += sacc[na][0] + sacc[na][1];
            rsum[1] += sacc[na][2] + sacc[na][3];
        }
#pragma unroll
        for (int d = 1; d <= 2; d <<= 1) {
            rsum[0] += __shfl_xor_sync(0xffffffffu, rsum[0], d);
            rsum[1] += __shfl_xor_sync(0xffffffffu, rsum[1], d);
        }
        lrow[0] = lrow[0] * fsc[0] + rsum[0];
        lrow[1] = lrow[1] * fsc[1] + rsum[1];

        // ---- pack P into bf16 hi/lo A-fragments
        uint32_t ph[4][4], pl[4][4];
#pragma unroll
        for (int j = 0; j < 4; j++) {
#pragma unroll
            for (int u = 0; u < 2; u++) {       // atom 2j+u
                const float* s4 = sacc[2 * j + u];
#pragma unroll
                for (int half = 0; half < 2; half++) {
                    float x = s4[half * 2 + 0], y = s4[half * 2 + 1];
                    __nv_bfloat162 hp = __float22bfloat162_rn(make_float2(x, y));
                    float2 hf2 = __bfloat1622float2(hp);
                    __nv_bfloat162 lp =
                        __float22bfloat162_rn(make_float2(x - hf2.x, y - hf2.y));
                    ph[j][u * 2 + half] = *reinterpret_cast<uint32_t*>(&hp);
                    pl[j][u * 2 + half] = *reinterpret_cast<uint32_t*>(&lp);
                }
            }
        }

        // ---- rescale O
#pragma unroll
        for (int na = 0; na < 8; na++) {
            oacc[na][0] *= fsc[0]; oacc[na][1] *= fsc[0];
            oacc[na][2] *= fsc[1]; oacc[na][3] *= fsc[1];
        }

        // ---- O += P V   (V^T fragments via ldmatrix.trans)
#pragma unroll
        for (int dp = 0; dp < 4; dp++) {
#pragma unroll
            for (int j = 0; j < 4; j++) {
                uint32_t vfh[4], vfl[4];
                const uint32_t va = stg + 2u * TILE_B +
                    (uint32_t)(j * 16 * 144 + dp * 32) + vadd;
                ldsm_x4_t(va, vfh);                  // Vh
                ldsm_x4_t(va + TILE_B, vfl);         // Vl
                mma_bf16(oacc[2 * dp],     ph[j], vfh[0], vfh[1]);
                mma_bf16(oacc[2 * dp + 1], ph[j], vfh[2], vfh[3]);
                mma_bf16(oacc[2 * dp],     ph[j], vfl[0], vfl[1]);
                mma_bf16(oacc[2 * dp + 1], ph[j], vfl[2], vfl[3]);
                mma_bf16(oacc[2 * dp],     pl[j], vfh[0], vfh[1]);
                mma_bf16(oacc[2 * dp + 1], pl[j], vfh[2], vfh[3]);
            }
        }
        __syncthreads();
    }

    // ---- finalize
    const float inv0 = 1.0f / lrow[0];
    const float inv1 = 1.0f / lrow[1];
    const int row0 = b * Tt + qt * 64 + wm * 16 + grp;
#pragma unroll
    for (int na = 0; na < 8; na++) {
        const int col = h * 64 + na * 8 + qid * 2;
        float2 w0 = make_float2(oacc[na][0] * inv0, oacc[na][1] * inv0);
        float2 w1 = make_float2(oacc[na][2] * inv1, oacc[na][3] * inv1);
        *(float2*)&g_AO[(size_t)row0 * HD + col]       = w0;
        *(float2*)&g_AO[(size_t)(row0 + 8) * HD + col] = w1;
    }
}

// ---------------------------------------------------------------------------
// Launch
// ---------------------------------------------------------------------------
extern "C" void kernel_launch(void* const* d_in, const int* in_sizes, int n_in,
                              void* d_out, int out_size) {
    const float* q  = (const float*)d_in[0];
    const float* k  = (const float*)d_in[1];
    const float* v  = (const float*)d_in[2];
    const float* Wq = (const float*)d_in[3];
    const float* Wk = (const float*)d_in[4];
    const float* Wv = (const float*)d_in[5];
    const float* Wo = (const float*)d_in[6];
    const float* bo = (const float*)d_in[7];
    float* out = (float*)d_out;

    void *pWqt, *pWkt, *pWvt, *pWot, *pAO;
    void *pQh, *pQl, *pKh, *pKl, *pVh, *pVl;
    cudaGetSymbolAddress(&pWqt, g_Wqt);
    cudaGetSymbolAddress(&pWkt, g_Wkt);
    cudaGetSymbolAddress(&pWvt, g_Wvt);
    cudaGetSymbolAddress(&pWot, g_Wot);
    cudaGetSymbolAddress(&pAO, g_AO);
    cudaGetSymbolAddress(&pQh, g_Qh);
    cudaGetSymbolAddress(&pQl, g_Ql);
    cudaGetSymbolAddress(&pKh, g_Kh);
    cudaGetSymbolAddress(&pKl, g_Kl);
    cudaGetSymbolAddress(&pVh, g_Vh);
    cudaGetSymbolAddress(&pVl, g_Vl);

    cudaFuncSetAttribute(gemm_mma,
                         cudaFuncAttributeMaxDynamicSharedMemorySize, GEMM_SMEM_BYTES);
    cudaFuncSetAttribute(flash2_kernel,
                         cudaFuncAttributeMaxDynamicSharedMemorySize, FLASH2_SMEM);

    pack_w_kernel<<<(Cc * HD) / 256, 256>>>(Wq, Wk, Wv, Wo);

    dim3 gg(HD / 128, MROWS / 128);
    gemm_mma<<<gg, 256, GEMM_SMEM_BYTES>>>(q, (const float*)pWqt, nullptr,
        (__nv_bfloat16*)pQh, (__nv_bfloat16*)pQl, MROWS, HD, Cc, nullptr);
    gemm_mma<<<gg, 256, GEMM_SMEM_BYTES>>>(k, (const float*)pWkt, nullptr,
        (__nv_bfloat16*)pKh, (__nv_bfloat16*)pKl, MROWS, HD, Cc, nullptr);
    gemm_mma<<<gg, 256, GEMM_SMEM_BYTES>>>(v, (const float*)pWvt, nullptr,
        (__nv_bfloat16*)pVh, (__nv_bfloat16*)pVl, MROWS, HD, Cc, nullptr);

    flash2_kernel<<<dim3(Tt / 64, Hh, Bb), 128, FLASH2_SMEM>>>();

    gemm_mma<<<dim3(Cc / 128, MROWS / 128), 256, GEMM_SMEM_BYTES>>>(
        (const float*)pAO, (const float*)pWot, out, nullptr, nullptr,
        MROWS, Cc, HD, bo);
}

// round 5
// speedup vs baseline: 2.2756x; 1.3051x over previous
#include <cuda_runtime.h>
#include <cuda_bf16.h>
#include <cstdint>

// Problem dims
constexpr int Bb = 4, Tt = 2048, Cc = 1024, Hh = 16, Dd = 64;
constexpr int MROWS = Bb * Tt;      // 8192
constexpr int HD    = Hh * Dd;      // 1024

// ---------------------------------------------------------------------------
// Scratch (device globals — no runtime allocation allowed)
// ---------------------------------------------------------------------------
// split activations [MROWS, C]
__device__ __nv_bfloat16 g_qh[MROWS * Cc], g_ql[MROWS * Cc];
__device__ __nv_bfloat16 g_kh[MROWS * Cc], g_kl[MROWS * Cc];
__device__ __nv_bfloat16 g_vh[MROWS * Cc], g_vl[MROWS * Cc];
// split weights: [N=HD, K=C] for QKV, [N=C, K=HD] for O
__device__ __nv_bfloat16 g_Wqh[HD * Cc], g_Wql[HD * Cc];
__device__ __nv_bfloat16 g_Wkh[HD * Cc], g_Wkl[HD * Cc];
__device__ __nv_bfloat16 g_Wvh[HD * Cc], g_Wvl[HD * Cc];
__device__ __nv_bfloat16 g_Woh[Cc * HD], g_Wol[Cc * HD];
// split projected Q/K/V [MROWS, HD]
__device__ __nv_bfloat16 g_Qh[MROWS * HD], g_Ql[MROWS * HD];
__device__ __nv_bfloat16 g_Kh[MROWS * HD], g_Kl[MROWS * HD];
__device__ __nv_bfloat16 g_Vh[MROWS * HD], g_Vl[MROWS * HD];
// split attention output [MROWS, HD]
__device__ __nv_bfloat16 g_AOh[MROWS * HD], g_AOl[MROWS * HD];

// ---------------------------------------------------------------------------
// Helpers
// ---------------------------------------------------------------------------
__device__ __forceinline__ uint32_t smem_u32(const void* p) {
    uint32_t a;
    asm("{ .reg .u64 t; cvta.to.shared.u64 t, %1; cvt.u32.u64 %0, t; }"
        : "=r"(a) : "l"(p));
    return a;
}
__device__ __forceinline__ void ldsm_x4(uint32_t addr, uint32_t* d) {
    asm volatile("ldmatrix.sync.aligned.m8n8.x4.shared.b16 {%0,%1,%2,%3}, [%4];"
        : "=r"(d[0]), "=r"(d[1]), "=r"(d[2]), "=r"(d[3]) : "r"(addr));
}
__device__ __forceinline__ void ldsm_x4_t(uint32_t addr, uint32_t* d) {
    asm volatile("ldmatrix.sync.aligned.m8n8.x4.trans.shared.b16 {%0,%1,%2,%3}, [%4];"
        : "=r"(d[0]), "=r"(d[1]), "=r"(d[2]), "=r"(d[3]) : "r"(addr));
}
__device__ __forceinline__ void mma_bf16(float* c, const uint32_t* a,
                                         uint32_t b0, uint32_t b1) {
    asm volatile("mma.sync.aligned.m16n8k16.row.col.f32.bf16.bf16.f32 "
        "{%0,%1,%2,%3}, {%4,%5,%6,%7}, {%8,%9}, {%0,%1,%2,%3};"
        : "+f"(c[0]), "+f"(c[1]), "+f"(c[2]), "+f"(c[3])
        : "r"(a[0]), "r"(a[1]), "r"(a[2]), "r"(a[3]), "r"(b0), "r"(b1));
}
__device__ __forceinline__ void cpa16(uint32_t dst, const void* src) {
    asm volatile("cp.async.cg.shared.global [%0], [%1], 16;" :: "r"(dst), "l"(src));
}
#define CP_COMMIT() asm volatile("cp.async.commit_group;" ::: "memory")
#define CP_WAIT0()  asm volatile("cp.async.wait_group 0;" ::: "memory")
#define CP_WAIT1()  asm volatile("cp.async.wait_group 1;" ::: "memory")

__device__ __forceinline__ float fast_exp2(float z) {
    z = fmaxf(z, -126.0f);
    float ni = rintf(z);
    float r = z - ni;
    float p = fmaf(r, 0.0013333558f, 0.0096181290f);
    p = fmaf(r, p, 0.0555041087f);
    p = fmaf(r, p, 0.2402265070f);
    p = fmaf(r, p, 0.6931471806f);
    p = fmaf(r, p, 1.0f);
    return p * __int_as_float(((int)ni + 127) << 23);
}

__device__ __forceinline__ void splitf(float x, __nv_bfloat16& h, __nv_bfloat16& l) {
    h = __float2bfloat16_rn(x);
    l = __float2bfloat16_rn(x - __bfloat162float(h));
}

// ---------------------------------------------------------------------------
// Pack weights (split to bf16 hi/lo): Wq/Wk/Wv [H,C,D] -> [N=HD,K=C];
// Wo [HD,C] -> [N=C,K=HD].
// ---------------------------------------------------------------------------
__global__ void pack_w_kernel(const float* __restrict__ Wq,
                              const float* __restrict__ Wk,
                              const float* __restrict__ Wv,
                              const float* __restrict__ Wo) {
    int idx = blockIdx.x * 256 + threadIdx.x;
    int n = idx >> 10;
    int c = idx & 1023;
    int src = (n >> 6) * (Cc * Dd) + c * Dd + (n & 63);
    splitf(Wq[src], g_Wqh[idx], g_Wql[idx]);
    splitf(Wk[src], g_Wkh[idx], g_Wkl[idx]);
    splitf(Wv[src], g_Wvh[idx], g_Wvl[idx]);
    splitf(Wo[c * Cc + n], g_Woh[idx], g_Wol[idx]);
}

// ---------------------------------------------------------------------------
// Split activations q,k,v fp32 -> bf16 hi/lo
// ---------------------------------------------------------------------------
__global__ void split_qkv_kernel(const float* __restrict__ q,
                                 const float* __restrict__ k,
                                 const float* __restrict__ v) {
    int i = (blockIdx.x * 256 + threadIdx.x) * 4;   // over MROWS*Cc, exact
#pragma unroll
    for (int t = 0; t < 3; t++) {
        const float* src = (t == 0) ? q : (t == 1) ? k : v;
        __nv_bfloat16* dh = (t == 0) ? g_qh : (t == 1) ? g_kh : g_vh;
        __nv_bfloat16* dl = (t == 0) ? g_ql : (t == 1) ? g_kl : g_vl;
        float4 x = *(const float4*)(src + i);
        __nv_bfloat16 h0, l0, h1, l1, h2, l2, h3, l3;
        splitf(x.x, h0, l0); splitf(x.y, h1, l1);
        splitf(x.z, h2, l2); splitf(x.w, h3, l3);
        __nv_bfloat162* ph = (__nv_bfloat162*)(dh + i);
        __nv_bfloat162* pl = (__nv_bfloat162*)(dl + i);
        ph[0] = __nv_bfloat162(h0, h1); ph[1] = __nv_bfloat162(h2, h3);
        pl[0] = __nv_bfloat162(l0, l1); pl[1] = __nv_bfloat162(l2, l3);
    }
}

// ---------------------------------------------------------------------------
// 3xBF16 mma.sync GEMM core. C[M,N] = (Ah+Al)[M,K] * (Bh+Bl)[N,K]^T.
// CTA 128x128x32, 256 thr (8 warps 2x4), warp 64x32, m16n8k16 atoms.
// smem: 2 stages x {Ah, Al, Bh, Bl}[128][40] bf16 (80B pitch).
// ---------------------------------------------------------------------------
constexpr int BPITCH = 40;                     // bf16; 80 bytes
constexpr int ASZ    = 128 * BPITCH * 2;       // 10240 bytes per array
constexpr int BSTAGE = 4 * ASZ;                // 40960
constexpr int GEMM_SMEM_BYTES = 2 * BSTAGE;    // 81920

__device__ __forceinline__ void gemm_core(
    const __nv_bfloat16* __restrict__ Ah, const __nv_bfloat16* __restrict__ Al,
    const __nv_bfloat16* __restrict__ Bh, const __nv_bfloat16* __restrict__ Bl,
    float* __restrict__ C, __nv_bfloat16* __restrict__ Ch,
    __nv_bfloat16* __restrict__ Cl,
    int M, int N, int K, const float* __restrict__ bias, int bm, int bn) {
    extern __shared__ char gsm[];
    const uint32_t sb = smem_u32(gsm);
    const int tid  = threadIdx.x;
    const int lane = tid & 31, wid = tid >> 5;
    const int wm = wid >> 2, wn = wid & 3;
    const int iters = K >> 5;

    // loader: thread covers row r, 32B half hf of each 64B tile row
    const int r = tid >> 1, hf = tid & 1;
    const size_t gA = (size_t)(bm * 128 + r) * K + hf * 16;
    const size_t gB = (size_t)(bn * 128 + r) * K + hf * 16;
    const uint32_t sByte = (uint32_t)(r * 80 + hf * 32);

    auto cp_stage = [&](int st, int it) {
        const uint32_t s0 = sb + st * BSTAGE + sByte;
        const size_t go = (size_t)it * 32;
        cpa16(s0,               Ah + gA + go); cpa16(s0 + 16,           Ah + gA + go + 8);
        cpa16(s0 + ASZ,         Al + gA + go); cpa16(s0 + ASZ + 16,     Al + gA + go + 8);
        cpa16(s0 + 2 * ASZ,     Bh + gB + go); cpa16(s0 + 2 * ASZ + 16, Bh + gB + go + 8);
        cpa16(s0 + 3 * ASZ,     Bl + gB + go); cpa16(s0 + 3 * ASZ + 16, Bl + gB + go + 8);
    };

    float acc[4][4][4];
#pragma unroll
    for (int ma = 0; ma < 4; ma++)
#pragma unroll
        for (int na = 0; na < 4; na++)
#pragma unroll
            for (int i = 0; i < 4; i++) acc[ma][na][i] = 0.f;

    cp_stage(0, 0);
    CP_COMMIT();

    // ldsm address components
    const uint32_t aadd = (uint32_t)((lane & 15) * 80 + (lane >> 4) * 16);
    const uint32_t badd = (uint32_t)(((lane & 7) + (lane >> 4) * 8) * 80 +
                                     ((lane >> 3) & 1) * 16);

#pragma unroll 1
    for (int it = 0; it < iters; ++it) {
        if (it + 1 < iters) {
            cp_stage((it + 1) & 1, it + 1);
            CP_COMMIT();
            CP_WAIT1();
        } else {
            CP_WAIT0();
        }
        __syncthreads();

        const uint32_t stb = sb + (it & 1) * BSTAGE;
        const uint32_t aBase = stb + (uint32_t)(wm * 64 * 80) + aadd;
        const uint32_t bBase = stb + 2u * ASZ + (uint32_t)(wn * 32 * 80) + badd;

#pragma unroll
        for (int ks = 0; ks < 2; ks++) {
            uint32_t ah[4][4], al[4][4], bh[2][4], bl[2][4];
#pragma unroll
            for (int ma = 0; ma < 4; ma++) {
                uint32_t ao = aBase + (uint32_t)(ma * 16 * 80 + ks * 32);
                ldsm_x4(ao, ah[ma]);
                ldsm_x4(ao + ASZ, al[ma]);
            }
#pragma unroll
            for (int pr = 0; pr < 2; pr++) {
                uint32_t bo = bBase + (uint32_t)(pr * 16 * 80 + ks * 32);
                ldsm_x4(bo, bh[pr]);
                ldsm_x4(bo + ASZ, bl[pr]);
            }
#pragma unroll
            for (int ma = 0; ma < 4; ma++)
#pragma unroll
                for (int pr = 0; pr < 2; pr++) {
                    float* c0 = acc[ma][2 * pr];
                    float* c1 = acc[ma][2 * pr + 1];
                    mma_bf16(c0, ah[ma], bh[pr][0], bh[pr][1]);
                    mma_bf16(c1, ah[ma], bh[pr][2], bh[pr][3]);
                    mma_bf16(c0, ah[ma], bl[pr][0], bl[pr][1]);
                    mma_bf16(c1, ah[ma], bl[pr][2], bl[pr][3]);
                    mma_bf16(c0, al[ma], bh[pr][0], bh[pr][1]);
                    mma_bf16(c1, al[ma], bh[pr][2], bh[pr][3]);
                }
        }
        __syncthreads();
    }

    const int grp = lane >> 2, qid = lane & 3;
#pragma unroll
    for (int ma = 0; ma < 4; ma++) {
        const int row0 = bm * 128 + wm * 64 + ma * 16 + grp;
#pragma unroll
        for (int na = 0; na < 4; na++) {
            const int col = bn * 128 + wn * 32 + na * 8 + qid * 2;
            if (Ch) {
#pragma unroll
                for (int half = 0; half < 2; half++) {
                    float x = acc[ma][na][half * 2 + 0];
                    float y = acc[ma][na][half * 2 + 1];
                    __nv_bfloat162 hp = __float22bfloat162_rn(make_float2(x, y));
                    float2 hf2 = __bfloat1622float2(hp);
                    __nv_bfloat162 lp =
                        __float22bfloat162_rn(make_float2(x - hf2.x, y - hf2.y));
                    size_t off = (size_t)(row0 + half * 8) * N + col;
                    *reinterpret_cast<__nv_bfloat162*>(&Ch[off]) = hp;
                    *reinterpret_cast<__nv_bfloat162*>(&Cl[off]) = lp;
                }
            } else {
                float bx = 0.f, by = 0.f;
                if (bias) { bx = bias[col]; by = bias[col + 1]; }
                float2 v0 = make_float2(acc[ma][na][0] + bx, acc[ma][na][1] + by);
                float2 v1 = make_float2(acc[ma][na][2] + bx, acc[ma][na][3] + by);
                *(float2*)&C[(size_t)row0 * N + col]       = v0;
                *(float2*)&C[(size_t)(row0 + 8) * N + col] = v1;
            }
        }
    }
}

// Fused Q/K/V projection: blockIdx.z selects the problem.
__global__ __launch_bounds__(256, 1) void qkv_gemm_kernel() {
    const __nv_bfloat16 *Ah, *Al, *Bh, *Bl;
    __nv_bfloat16 *Ch, *Cl;
    if (blockIdx.z == 0) {
        Ah = g_qh; Al = g_ql; Bh = g_Wqh; Bl = g_Wql; Ch = g_Qh; Cl = g_Ql;
    } else if (blockIdx.z == 1) {
        Ah = g_kh; Al = g_kl; Bh = g_Wkh; Bl = g_Wkl; Ch = g_Kh; Cl = g_Kl;
    } else {
        Ah = g_vh; Al = g_vl; Bh = g_Wvh; Bl = g_Wvl; Ch = g_Vh; Cl = g_Vl;
    }
    gemm_core(Ah, Al, Bh, Bl, nullptr, Ch, Cl, MROWS, HD, Cc, nullptr,
              blockIdx.y, blockIdx.x);
}

// Output projection (+bias) to fp32.
__global__ __launch_bounds__(256, 1) void out_gemm_kernel(
    float* __restrict__ out, const float* __restrict__ bias) {
    gemm_core(g_AOh, g_AOl, g_Woh, g_Wol, out, nullptr, nullptr,
              MROWS, Cc, HD, bias, blockIdx.y, blockIdx.x);
}

// ---------------------------------------------------------------------------
// Tensor-core causal flash attention, 3xBF16 (unchanged core; bf16-split out).
// CTA: 128 thr (4 warps), BQ=64 (warp = m16), BK=64, D=64.
// ---------------------------------------------------------------------------
constexpr int FP = 72;                       // bf16 pitch (144 bytes)
constexpr int TILE_B = 64 * FP * 2;          // 9216 bytes per array
constexpr int F_QH = 0, F_QL = TILE_B;
constexpr int F_ST0 = 2 * TILE_B;
constexpr int FLASH2_SMEM = (2 + 8) * TILE_B;  // 92160

__global__ __launch_bounds__(128) void flash2_kernel() {
    extern __shared__ char fsm[];
    const uint32_t sb = smem_u32(fsm);
    const int tid = threadIdx.x;
    const int lane = tid & 31, wm = tid >> 5;
    const int qt = blockIdx.x, h = blockIdx.y, b = blockIdx.z;

    const size_t qrow = (size_t)(b * Tt + qt * 64) * HD + h * 64;

    const int crow = tid >> 1, cseg = tid & 1;
    auto copy_tile = [&](uint32_t soff, const __nv_bfloat16* g) {
        const char* gp = (const char*)(g) + (size_t)crow * (HD * 2) + cseg * 64;
        uint32_t sp = sb + soff + crow * 144 + cseg * 64;
#pragma unroll
        for (int i = 0; i < 4; i++) cpa16(sp + i * 16, gp + i * 16);
    };

    copy_tile(F_QH, g_Qh + qrow);
    copy_tile(F_QL, g_Ql + qrow);
    {
        const size_t krow = (size_t)(b * Tt) * HD + h * 64;
        copy_tile(F_ST0 + 0 * TILE_B, g_Kh + krow);
        copy_tile(F_ST0 + 1 * TILE_B, g_Kl + krow);
        copy_tile(F_ST0 + 2 * TILE_B, g_Vh + krow);
        copy_tile(F_ST0 + 3 * TILE_B, g_Vl + krow);
    }
    CP_COMMIT();
    CP_WAIT0();
    __syncthreads();

    uint32_t qh[4][4], ql[4][4];
    {
        const uint32_t qa = sb + (uint32_t)((wm * 16 + (lane & 15)) * 144 +
                                            (lane >> 4) * 16);
#pragma unroll
        for (int ks = 0; ks < 4; ks++) {
            ldsm_x4(F_QH + qa + ks * 32, qh[ks]);
            ldsm_x4(F_QL + qa + ks * 32, ql[ks]);
        }
    }

    float oacc[8][4];
#pragma unroll
    for (int na = 0; na < 8; na++)
#pragma unroll
        for (int i = 0; i < 4; i++) oacc[na][i] = 0.f;
    float mrow[2] = {-3.0e38f, -3.0e38f};
    float lrow[2] = {0.f, 0.f};

    constexpr float SC = 0.045084971874737f;   // (1/32) * log2(e)

    const uint32_t kadd = (uint32_t)(((lane & 7) + (lane >> 4) * 8) * 144 +
                                     ((lane >> 3) & 1) * 16);
    const uint32_t vadd = (uint32_t)(((lane & 7) + ((lane >> 3) & 1) * 8) * 144 +
                                     (lane >> 4) * 16);
    const int grp = lane >> 2, qid = lane & 3;

#pragma unroll 1
    for (int kt = 0; kt <= qt; kt++) {
        const uint32_t stg = sb + F_ST0 + (uint32_t)((kt & 1) * 4 * TILE_B);

        if (kt < qt) {
            const size_t krow = (size_t)(b * Tt + (kt + 1) * 64) * HD + h * 64;
            const uint32_t nst = F_ST0 + (uint32_t)(((kt + 1) & 1) * 4 * TILE_B);
            copy_tile(nst + 0 * TILE_B, g_Kh + krow);
            copy_tile(nst + 1 * TILE_B, g_Kl + krow);
            copy_tile(nst + 2 * TILE_B, g_Vh + krow);
            copy_tile(nst + 3 * TILE_B, g_Vl + krow);
            CP_COMMIT();
            CP_WAIT1();
        } else {
            CP_WAIT0();
        }
        __syncthreads();

        float sacc[8][4];
#pragma unroll
        for (int na = 0; na < 8; na++)
#pragma unroll
            for (int i = 0; i < 4; i++) sacc[na][i] = 0.f;

#pragma unroll
        for (int ks = 0; ks < 4; ks++) {
#pragma unroll
            for (int pr = 0; pr < 4; pr++) {
                uint32_t kfh[4], kfl[4];
                const uint32_t ka = stg + (uint32_t)(pr * 16 * 144 + ks * 32) + kadd;
                ldsm_x4(ka, kfh);
                ldsm_x4(ka + TILE_B, kfl);
                mma_bf16(sacc[2 * pr],     qh[ks], kfh[0], kfh[1]);
                mma_bf16(sacc[2 * pr + 1], qh[ks], kfh[2], kfh[3]);
                mma_bf16(sacc[2 * pr],     qh[ks], kfl[0], kfl[1]);
                mma_bf16(sacc[2 * pr + 1], qh[ks], kfl[2], kfl[3]);
                mma_bf16(sacc[2 * pr],     ql[ks], kfh[0], kfh[1]);
                mma_bf16(sacc[2 * pr + 1], ql[ks], kfh[2], kfh[3]);
            }
        }

        if (kt == qt) {
            const int r0 = wm * 16 + grp;
#pragma unroll
            for (int na = 0; na < 8; na++) {
                const int c0 = na * 8 + qid * 2;
                if (c0 > r0)     sacc[na][0] = -3.0e38f;
                if (c0 + 1 > r0) sacc[na][1] = -3.0e38f;
                if (c0 > r0 + 8)     sacc[na][2] = -3.0e38f;
                if (c0 + 1 > r0 + 8) sacc[na][3] = -3.0e38f;
            }
        }

        float rmax[2];
        rmax[0] = sacc[0][0]; rmax[1] = sacc[0][2];
#pragma unroll
        for (int na = 0; na < 8; na++) {
            rmax[0] = fmaxf(rmax[0], fmaxf(sacc[na][0], sacc[na][1]));
            rmax[1] = fmaxf(rmax[1], fmaxf(sacc[na][2], sacc[na][3]));
        }
#pragma unroll
        for (int d = 1; d <= 2; d <<= 1) {
            rmax[0] = fmaxf(rmax[0], __shfl_xor_sync(0xffffffffu, rmax[0], d));
            rmax[1] = fmaxf(rmax[1], __shfl_xor_sync(0xffffffffu, rmax[1], d));
        }
        float mnew[2], fsc[2];
#pragma unroll
        for (int i = 0; i < 2; i++) {
            mnew[i] = fmaxf(mrow[i], rmax[i]);
            fsc[i] = fast_exp2((mrow[i] - mnew[i]) * SC);
            mrow[i] = mnew[i];
        }

        float rsum[2] = {0.f, 0.f};
#pragma unroll
        for (int na = 0; na < 8; na++) {
            sacc[na][0] = fast_exp2((sacc[na][0] - mnew[0]) * SC);
            sacc[na][1] = fast_exp2((sacc[na][1] - mnew[0]) * SC);
            sacc[na][2] = fast_exp2((sacc[na][2] - mnew[1]) * SC);
            sacc[na][3] = fast_exp2((sacc[na][3] - mnew[1]) * SC);
            rsum[0] += sacc[na][0] + sacc[na][1];
            rsum[1] += sacc[na][2] + sacc[na][3];
        }
#pragma unroll
        for (int d = 1; d <= 2; d <<= 1) {
            rsum[0] += __shfl_xor_sync(0xffffffffu, rsum[0], d);
            rsum[1] += __shfl_xor_sync(0xffffffffu, rsum[1], d);
        }
        lrow[0] = lrow[0] * fsc[0] + rsum[0];
        lrow[1] = lrow[1] * fsc[1] + rsum[1];

        uint32_t ph[4][4], pl[4][4];
#pragma unroll
        for (int j = 0; j < 4; j++) {
#pragma unroll
            for (int u = 0; u < 2; u++) {
                const float* s4 = sacc[2 * j + u];
#pragma unroll
                for (int half = 0; half < 2; half++) {
                    float x = s4[half * 2 + 0], y = s4[half * 2 + 1];
                    __nv_bfloat162 hp = __float22bfloat162_rn(make_float2(x, y));
                    float2 hf2 = __bfloat1622float2(hp);
                    __nv_bfloat162 lp =
                        __float22bfloat162_rn(make_float2(x - hf2.x, y - hf2.y));
                    ph[j][u * 2 + half] = *reinterpret_cast<uint32_t*>(&hp);
                    pl[j][u * 2 + half] = *reinterpret_cast<uint32_t*>(&lp);
                }
            }
        }

#pragma unroll
        for (int na = 0; na < 8; na++) {
            oacc[na][0] *= fsc[0]; oacc[na][1] *= fsc[0];
            oacc[na][2] *= fsc[1]; oacc[na][3] *= fsc[1];
        }

#pragma unroll
        for (int dp = 0; dp < 4; dp++) {
#pragma unroll
            for (int j = 0; j < 4; j++) {
                uint32_t vfh[4], vfl[4];
                const uint32_t va = stg + 2u * TILE_B +
                    (uint32_t)(j * 16 * 144 + dp * 32) + vadd;
                ldsm_x4_t(va, vfh);
                ldsm_x4_t(va + TILE_B, vfl);
                mma_bf16(oacc[2 * dp],     ph[j], vfh[0], vfh[1]);
                mma_bf16(oacc[2 * dp + 1], ph[j], vfh[2], vfh[3]);
                mma_bf16(oacc[2 * dp],     ph[j], vfl[0], vfl[1]);
                mma_bf16(oacc[2 * dp + 1], ph[j], vfl[2], vfl[3]);
                mma_bf16(oacc[2 * dp],     pl[j], vfh[0], vfh[1]);
                mma_bf16(oacc[2 * dp + 1], pl[j], vfh[2], vfh[3]);
            }
        }
        __syncthreads();
    }

    // finalize: split O to bf16 hi/lo for the output-projection GEMM
    const float inv0 = 1.0f / lrow[0];
    const float inv1 = 1.0f / lrow[1];
    const int row0 = b * Tt + qt * 64 + wm * 16 + grp;
#pragma unroll
    for (int na = 0; na < 8; na++) {
        const int col = h * 64 + na * 8 + qid * 2;
#pragma unroll
        for (int half = 0; half < 2; half++) {
            float inv = half ? inv1 : inv0;
            float x = oacc[na][half * 2 + 0] * inv;
            float y = oacc[na][half * 2 + 1] * inv;
            __nv_bfloat162 hp = __float22bfloat162_rn(make_float2(x, y));
            float2 hf2 = __bfloat1622float2(hp);
            __nv_bfloat162 lp =
                __float22bfloat162_rn(make_float2(x - hf2.x, y - hf2.y));
            size_t off = (size_t)(row0 + half * 8) * HD + col;
            *reinterpret_cast<__nv_bfloat162*>(&g_AOh[off]) = hp;
            *reinterpret_cast<__nv_bfloat162*>(&g_AOl[off]) = lp;
        }
    }
}

// ---------------------------------------------------------------------------
// Launch
// ---------------------------------------------------------------------------
extern "C" void kernel_launch(void* const* d_in, const int* in_sizes, int n_in,
                              void* d_out, int out_size) {
    const float* q  = (const float*)d_in[0];
    const float* k  = (const float*)d_in[1];
    const float* v  = (const float*)d_in[2];
    const float* Wq = (const float*)d_in[3];
    const float* Wk = (const float*)d_in[4];
    const float* Wv = (const float*)d_in[5];
    const float* Wo = (const float*)d_in[6];
    const float* bo = (const float*)d_in[7];
    float* out = (float*)d_out;

    cudaFuncSetAttribute(qkv_gemm_kernel,
                         cudaFuncAttributeMaxDynamicSharedMemorySize, GEMM_SMEM_BYTES);
    cudaFuncSetAttribute(out_gemm_kernel,
                         cudaFuncAttributeMaxDynamicSharedMemorySize, GEMM_SMEM_BYTES);
    cudaFuncSetAttribute(flash2_kernel,
                         cudaFuncAttributeMaxDynamicSharedMemorySize, FLASH2_SMEM);

    pack_w_kernel<<<(Cc * HD) / 256, 256>>>(Wq, Wk, Wv, Wo);
    split_qkv_kernel<<<(MROWS * Cc) / (256 * 4), 256>>>(q, k, v);

    qkv_gemm_kernel<<<dim3(HD / 128, MROWS / 128, 3), 256, GEMM_SMEM_BYTES>>>();

    flash2_kernel<<<dim3(Tt / 64, Hh, Bb), 128, FLASH2_SMEM>>>();

    out_gemm_kernel<<<dim3(Cc / 128, MROWS / 128), 256, GEMM_SMEM_BYTES>>>(out, bo);
}

// round 6
// speedup vs baseline: 2.3782x; 1.0451x over previous
#include <cuda_runtime.h>
#include <cuda_bf16.h>
#include <cstdint>

// Problem dims
constexpr int Bb = 4, Tt = 2048, Cc = 1024, Hh = 16, Dd = 64;
constexpr int MROWS = Bb * Tt;      // 8192
constexpr int HD    = Hh * Dd;      // 1024

// ---------------------------------------------------------------------------
// Scratch (device globals — no runtime allocation allowed)
// ---------------------------------------------------------------------------
__device__ __nv_bfloat16 g_qh[MROWS * Cc], g_ql[MROWS * Cc];
__device__ __nv_bfloat16 g_kh[MROWS * Cc], g_kl[MROWS * Cc];
__device__ __nv_bfloat16 g_vh[MROWS * Cc], g_vl[MROWS * Cc];
__device__ __nv_bfloat16 g_Wqh[HD * Cc], g_Wql[HD * Cc];
__device__ __nv_bfloat16 g_Wkh[HD * Cc], g_Wkl[HD * Cc];
__device__ __nv_bfloat16 g_Wvh[HD * Cc], g_Wvl[HD * Cc];
__device__ __nv_bfloat16 g_Woh[Cc * HD], g_Wol[Cc * HD];
__device__ __nv_bfloat16 g_Qh[MROWS * HD], g_Ql[MROWS * HD];
__device__ __nv_bfloat16 g_Kh[MROWS * HD], g_Kl[MROWS * HD];
__device__ __nv_bfloat16 g_Vh[MROWS * HD], g_Vl[MROWS * HD];
__device__ __nv_bfloat16 g_AOh[MROWS * HD], g_AOl[MROWS * HD];

// ---------------------------------------------------------------------------
// Helpers
// ---------------------------------------------------------------------------
__device__ __forceinline__ uint32_t smem_u32(const void* p) {
    uint32_t a;
    asm("{ .reg .u64 t; cvta.to.shared.u64 t, %1; cvt.u32.u64 %0, t; }"
        : "=r"(a) : "l"(p));
    return a;
}
__device__ __forceinline__ void ldsm_x4(uint32_t addr, uint32_t* d) {
    asm volatile("ldmatrix.sync.aligned.m8n8.x4.shared.b16 {%0,%1,%2,%3}, [%4];"
        : "=r"(d[0]), "=r"(d[1]), "=r"(d[2]), "=r"(d[3]) : "r"(addr));
}
__device__ __forceinline__ void ldsm_x4_t(uint32_t addr, uint32_t* d) {
    asm volatile("ldmatrix.sync.aligned.m8n8.x4.trans.shared.b16 {%0,%1,%2,%3}, [%4];"
        : "=r"(d[0]), "=r"(d[1]), "=r"(d[2]), "=r"(d[3]) : "r"(addr));
}
__device__ __forceinline__ void mma_bf16(float* c, const uint32_t* a,
                                         uint32_t b0, uint32_t b1) {
    asm volatile("mma.sync.aligned.m16n8k16.row.col.f32.bf16.bf16.f32 "
        "{%0,%1,%2,%3}, {%4,%5,%6,%7}, {%8,%9}, {%0,%1,%2,%3};"
        : "+f"(c[0]), "+f"(c[1]), "+f"(c[2]), "+f"(c[3])
        : "r"(a[0]), "r"(a[1]), "r"(a[2]), "r"(a[3]), "r"(b0), "r"(b1));
}
__device__ __forceinline__ void cpa16(uint32_t dst, const void* src) {
    asm volatile("cp.async.cg.shared.global [%0], [%1], 16;" :: "r"(dst), "l"(src));
}
#define CP_COMMIT() asm volatile("cp.async.commit_group;" ::: "memory")
#define CP_WAIT0()  asm volatile("cp.async.wait_group 0;" ::: "memory")
#define CP_WAIT1()  asm volatile("cp.async.wait_group 1;" ::: "memory")

__device__ __forceinline__ float fast_exp2(float z) {
    z = fmaxf(z, -126.0f);
    float ni = rintf(z);
    float r = z - ni;
    float p = fmaf(r, 0.0013333558f, 0.0096181290f);
    p = fmaf(r, p, 0.0555041087f);
    p = fmaf(r, p, 0.2402265070f);
    p = fmaf(r, p, 0.6931471806f);
    p = fmaf(r, p, 1.0f);
    return p * __int_as_float(((int)ni + 127) << 23);
}

__device__ __forceinline__ void splitf(float x, __nv_bfloat16& h, __nv_bfloat16& l) {
    h = __float2bfloat16_rn(x);
    l = __float2bfloat16_rn(x - __bfloat162float(h));
}

// ---------------------------------------------------------------------------
// Pack weights (split to bf16 hi/lo)
// ---------------------------------------------------------------------------
__global__ void pack_w_kernel(const float* __restrict__ Wq,
                              const float* __restrict__ Wk,
                              const float* __restrict__ Wv,
                              const float* __restrict__ Wo) {
    int idx = blockIdx.x * 256 + threadIdx.x;
    int n = idx >> 10;
    int c = idx & 1023;
    int src = (n >> 6) * (Cc * Dd) + c * Dd + (n & 63);
    splitf(Wq[src], g_Wqh[idx], g_Wql[idx]);
    splitf(Wk[src], g_Wkh[idx], g_Wkl[idx]);
    splitf(Wv[src], g_Wvh[idx], g_Wvl[idx]);
    splitf(Wo[c * Cc + n], g_Woh[idx], g_Wol[idx]);
}

// ---------------------------------------------------------------------------
// Split activations q,k,v fp32 -> bf16 hi/lo
// ---------------------------------------------------------------------------
__global__ void split_qkv_kernel(const float* __restrict__ q,
                                 const float* __restrict__ k,
                                 const float* __restrict__ v) {
    int i = (blockIdx.x * 256 + threadIdx.x) * 4;
#pragma unroll
    for (int t = 0; t < 3; t++) {
        const float* src = (t == 0) ? q : (t == 1) ? k : v;
        __nv_bfloat16* dh = (t == 0) ? g_qh : (t == 1) ? g_kh : g_vh;
        __nv_bfloat16* dl = (t == 0) ? g_ql : (t == 1) ? g_kl : g_vl;
        float4 x = *(const float4*)(src + i);
        __nv_bfloat16 h0, l0, h1, l1, h2, l2, h3, l3;
        splitf(x.x, h0, l0); splitf(x.y, h1, l1);
        splitf(x.z, h2, l2); splitf(x.w, h3, l3);
        __nv_bfloat162* ph = (__nv_bfloat162*)(dh + i);
        __nv_bfloat162* pl = (__nv_bfloat162*)(dl + i);
        ph[0] = __nv_bfloat162(h0, h1); ph[1] = __nv_bfloat162(h2, h3);
        pl[0] = __nv_bfloat162(l0, l1); pl[1] = __nv_bfloat162(l2, l3);
    }
}

// ---------------------------------------------------------------------------
// 3xBF16 mma.sync GEMM core, split-type-outermost mma scheduling.
// CTA 128x128x32, 256 thr (8 warps 2x4), warp 64x32, m16n8k16 atoms.
// ---------------------------------------------------------------------------
constexpr int BPITCH = 40;
constexpr int ASZ    = 128 * BPITCH * 2;       // 10240 bytes
constexpr int BSTAGE = 4 * ASZ;                // 40960
constexpr int GEMM_SMEM_BYTES = 2 * BSTAGE;    // 81920

__device__ __forceinline__ void gemm_core(
    const __nv_bfloat16* __restrict__ Ah, const __nv_bfloat16* __restrict__ Al,
    const __nv_bfloat16* __restrict__ Bh, const __nv_bfloat16* __restrict__ Bl,
    float* __restrict__ C, __nv_bfloat16* __restrict__ Ch,
    __nv_bfloat16* __restrict__ Cl,
    int M, int N, int K, const float* __restrict__ bias, int bm, int bn) {
    extern __shared__ char gsm[];
    const uint32_t sb = smem_u32(gsm);
    const int tid  = threadIdx.x;
    const int lane = tid & 31, wid = tid >> 5;
    const int wm = wid >> 2, wn = wid & 3;
    const int iters = K >> 5;

    const int r = tid >> 1, hf = tid & 1;
    const size_t gA = (size_t)(bm * 128 + r) * K + hf * 16;
    const size_t gB = (size_t)(bn * 128 + r) * K + hf * 16;
    const uint32_t sByte = (uint32_t)(r * 80 + hf * 32);

    auto cp_stage = [&](int st, int it) {
        const uint32_t s0 = sb + st * BSTAGE + sByte;
        const size_t go = (size_t)it * 32;
        cpa16(s0,               Ah + gA + go); cpa16(s0 + 16,           Ah + gA + go + 8);
        cpa16(s0 + ASZ,         Al + gA + go); cpa16(s0 + ASZ + 16,     Al + gA + go + 8);
        cpa16(s0 + 2 * ASZ,     Bh + gB + go); cpa16(s0 + 2 * ASZ + 16, Bh + gB + go + 8);
        cpa16(s0 + 3 * ASZ,     Bl + gB + go); cpa16(s0 + 3 * ASZ + 16, Bl + gB + go + 8);
    };

    float acc[4][4][4];
#pragma unroll
    for (int ma = 0; ma < 4; ma++)
#pragma unroll
        for (int na = 0; na < 4; na++)
#pragma unroll
            for (int i = 0; i < 4; i++) acc[ma][na][i] = 0.f;

    cp_stage(0, 0);
    CP_COMMIT();

    const uint32_t aadd = (uint32_t)((lane & 15) * 80 + (lane >> 4) * 16);
    const uint32_t badd = (uint32_t)(((lane & 7) + (lane >> 4) * 8) * 80 +
                                     ((lane >> 3) & 1) * 16);

#pragma unroll 1
    for (int it = 0; it < iters; ++it) {
        if (it + 1 < iters) {
            cp_stage((it + 1) & 1, it + 1);
            CP_COMMIT();
            CP_WAIT1();
        } else {
            CP_WAIT0();
        }
        __syncthreads();

        const uint32_t stb = sb + (it & 1) * BSTAGE;
        const uint32_t aBase = stb + (uint32_t)(wm * 64 * 80) + aadd;
        const uint32_t bBase = stb + 2u * ASZ + (uint32_t)(wn * 32 * 80) + badd;

#pragma unroll
        for (int ks = 0; ks < 2; ks++) {
            uint32_t ah[4][4], al[4][4], bh[2][4], bl[2][4];
#pragma unroll
            for (int ma = 0; ma < 4; ma++) {
                uint32_t ao = aBase + (uint32_t)(ma * 16 * 80 + ks * 32);
                ldsm_x4(ao, ah[ma]);
                ldsm_x4(ao + ASZ, al[ma]);
            }
#pragma unroll
            for (int pr = 0; pr < 2; pr++) {
                uint32_t bo = bBase + (uint32_t)(pr * 16 * 80 + ks * 32);
                ldsm_x4(bo, bh[pr]);
                ldsm_x4(bo + ASZ, bl[pr]);
            }
            // split-type-outermost: same-acc reuse distance = 16 mmas
#pragma unroll
            for (int ma = 0; ma < 4; ma++)
#pragma unroll
                for (int pr = 0; pr < 2; pr++) {
                    mma_bf16(acc[ma][2 * pr],     ah[ma], bh[pr][0], bh[pr][1]);
                    mma_bf16(acc[ma][2 * pr + 1], ah[ma], bh[pr][2], bh[pr][3]);
                }
#pragma unroll
            for (int ma = 0; ma < 4; ma++)
#pragma unroll
                for (int pr = 0; pr < 2; pr++) {
                    mma_bf16(acc[ma][2 * pr],     ah[ma], bl[pr][0], bl[pr][1]);
                    mma_bf16(acc[ma][2 * pr + 1], ah[ma], bl[pr][2], bl[pr][3]);
                }
#pragma unroll
            for (int ma = 0; ma < 4; ma++)
#pragma unroll
                for (int pr = 0; pr < 2; pr++) {
                    mma_bf16(acc[ma][2 * pr],     al[ma], bh[pr][0], bh[pr][1]);
                    mma_bf16(acc[ma][2 * pr + 1], al[ma], bh[pr][2], bh[pr][3]);
                }
        }
        __syncthreads();
    }

    const int grp = lane >> 2, qid = lane & 3;
#pragma unroll
    for (int ma = 0; ma < 4; ma++) {
        const int row0 = bm * 128 + wm * 64 + ma * 16 + grp;
#pragma unroll
        for (int na = 0; na < 4; na++) {
            const int col = bn * 128 + wn * 32 + na * 8 + qid * 2;
            if (Ch) {
#pragma unroll
                for (int half = 0; half < 2; half++) {
                    float x = acc[ma][na][half * 2 + 0];
                    float y = acc[ma][na][half * 2 + 1];
                    __nv_bfloat162 hp = __float22bfloat162_rn(make_float2(x, y));
                    float2 hf2 = __bfloat1622float2(hp);
                    __nv_bfloat162 lp =
                        __float22bfloat162_rn(make_float2(x - hf2.x, y - hf2.y));
                    size_t off = (size_t)(row0 + half * 8) * N + col;
                    *reinterpret_cast<__nv_bfloat162*>(&Ch[off]) = hp;
                    *reinterpret_cast<__nv_bfloat162*>(&Cl[off]) = lp;
                }
            } else {
                float bx = 0.f, by = 0.f;
                if (bias) { bx = bias[col]; by = bias[col + 1]; }
                float2 v0 = make_float2(acc[ma][na][0] + bx, acc[ma][na][1] + by);
                float2 v1 = make_float2(acc[ma][na][2] + bx, acc[ma][na][3] + by);
                *(float2*)&C[(size_t)row0 * N + col]       = v0;
                *(float2*)&C[(size_t)(row0 + 8) * N + col] = v1;
            }
        }
    }
}

__global__ __launch_bounds__(256, 1) void qkv_gemm_kernel() {
    const __nv_bfloat16 *Ah, *Al, *Bh, *Bl;
    __nv_bfloat16 *Ch, *Cl;
    if (blockIdx.z == 0) {
        Ah = g_qh; Al = g_ql; Bh = g_Wqh; Bl = g_Wql; Ch = g_Qh; Cl = g_Ql;
    } else if (blockIdx.z == 1) {
        Ah = g_kh; Al = g_kl; Bh = g_Wkh; Bl = g_Wkl; Ch = g_Kh; Cl = g_Kl;
    } else {
        Ah = g_vh; Al = g_vl; Bh = g_Wvh; Bl = g_Wvl; Ch = g_Vh; Cl = g_Vl;
    }
    gemm_core(Ah, Al, Bh, Bl, nullptr, Ch, Cl, MROWS, HD, Cc, nullptr,
              blockIdx.y, blockIdx.x);
}

__global__ __launch_bounds__(256, 1) void out_gemm_kernel(
    float* __restrict__ out, const float* __restrict__ bias) {
    gemm_core(g_AOh, g_AOl, g_Woh, g_Wol, out, nullptr, nullptr,
              MROWS, Cc, HD, bias, blockIdx.y, blockIdx.x);
}

// ---------------------------------------------------------------------------
// Tensor-core causal flash attention, 3xBF16, split-type-outermost scheduling.
// CTA: 128 thr (4 warps), BQ=64 (warp = m16), BK=64, D=64.
// ---------------------------------------------------------------------------
constexpr int FP = 72;
constexpr int TILE_B = 64 * FP * 2;          // 9216 bytes
constexpr int F_QH = 0, F_QL = TILE_B;
constexpr int F_ST0 = 2 * TILE_B;
constexpr int FLASH2_SMEM = (2 + 8) * TILE_B;  // 92160

__global__ __launch_bounds__(128, 2) void flash2_kernel() {
    extern __shared__ char fsm[];
    const uint32_t sb = smem_u32(fsm);
    const int tid = threadIdx.x;
    const int lane = tid & 31, wm = tid >> 5;
    const int qt = blockIdx.x, h = blockIdx.y, b = blockIdx.z;

    const size_t qrow = (size_t)(b * Tt + qt * 64) * HD + h * 64;

    const int crow = tid >> 1, cseg = tid & 1;
    auto copy_tile = [&](uint32_t soff, const __nv_bfloat16* g) {
        const char* gp = (const char*)(g) + (size_t)crow * (HD * 2) + cseg * 64;
        uint32_t sp = sb + soff + crow * 144 + cseg * 64;
#pragma unroll
        for (int i = 0; i < 4; i++) cpa16(sp + i * 16, gp + i * 16);
    };

    copy_tile(F_QH, g_Qh + qrow);
    copy_tile(F_QL, g_Ql + qrow);
    {
        const size_t krow = (size_t)(b * Tt) * HD + h * 64;
        copy_tile(F_ST0 + 0 * TILE_B, g_Kh + krow);
        copy_tile(F_ST0 + 1 * TILE_B, g_Kl + krow);
        copy_tile(F_ST0 + 2 * TILE_B, g_Vh + krow);
        copy_tile(F_ST0 + 3 * TILE_B, g_Vl + krow);
    }
    CP_COMMIT();
    CP_WAIT0();
    __syncthreads();

    uint32_t qh[4][4], ql[4][4];
    {
        const uint32_t qa = sb + (uint32_t)((wm * 16 + (lane & 15)) * 144 +
                                            (lane >> 4) * 16);
#pragma unroll
        for (int ks = 0; ks < 4; ks++) {
            ldsm_x4(F_QH + qa + ks * 32, qh[ks]);
            ldsm_x4(F_QL + qa + ks * 32, ql[ks]);
        }
    }

    float oacc[8][4];
#pragma unroll
    for (int na = 0; na < 8; na++)
#pragma unroll
        for (int i = 0; i < 4; i++) oacc[na][i] = 0.f;
    float mrow[2] = {-3.0e38f, -3.0e38f};
    float lrow[2] = {0.f, 0.f};

    constexpr float SC = 0.045084971874737f;   // (1/32) * log2(e)

    const uint32_t kadd = (uint32_t)(((lane & 7) + (lane >> 4) * 8) * 144 +
                                     ((lane >> 3) & 1) * 16);
    const uint32_t vadd = (uint32_t)(((lane & 7) + ((lane >> 3) & 1) * 8) * 144 +
                                     (lane >> 4) * 16);
    const int grp = lane >> 2, qid = lane & 3;

#pragma unroll 1
    for (int kt = 0; kt <= qt; kt++) {
        const uint32_t stg = sb + F_ST0 + (uint32_t)((kt & 1) * 4 * TILE_B);

        if (kt < qt) {
            const size_t krow = (size_t)(b * Tt + (kt + 1) * 64) * HD + h * 64;
            const uint32_t nst = F_ST0 + (uint32_t)(((kt + 1) & 1) * 4 * TILE_B);
            copy_tile(nst + 0 * TILE_B, g_Kh + krow);
            copy_tile(nst + 1 * TILE_B, g_Kl + krow);
            copy_tile(nst + 2 * TILE_B, g_Vh + krow);
            copy_tile(nst + 3 * TILE_B, g_Vl + krow);
            CP_COMMIT();
            CP_WAIT1();
        } else {
            CP_WAIT0();
        }
        __syncthreads();

        // ---- S = Q K^T: hoist all K fragments per ks, type-outermost issue
        float sacc[8][4];
#pragma unroll
        for (int na = 0; na < 8; na++)
#pragma unroll
            for (int i = 0; i < 4; i++) sacc[na][i] = 0.f;

#pragma unroll
        for (int ks = 0; ks < 4; ks++) {
            uint32_t kfh[4][4], kfl[4][4];
#pragma unroll
            for (int pr = 0; pr < 4; pr++) {
                const uint32_t ka = stg + (uint32_t)(pr * 16 * 144 + ks * 32) + kadd;
                ldsm_x4(ka, kfh[pr]);
                ldsm_x4(ka + TILE_B, kfl[pr]);
            }
#pragma unroll
            for (int pr = 0; pr < 4; pr++) {
                mma_bf16(sacc[2 * pr],     qh[ks], kfh[pr][0], kfh[pr][1]);
                mma_bf16(sacc[2 * pr + 1], qh[ks], kfh[pr][2], kfh[pr][3]);
            }
#pragma unroll
            for (int pr = 0; pr < 4; pr++) {
                mma_bf16(sacc[2 * pr],     qh[ks], kfl[pr][0], kfl[pr][1]);
                mma_bf16(sacc[2 * pr + 1], qh[ks], kfl[pr][2], kfl[pr][3]);
            }
#pragma unroll
            for (int pr = 0; pr < 4; pr++) {
                mma_bf16(sacc[2 * pr],     ql[ks], kfh[pr][0], kfh[pr][1]);
                mma_bf16(sacc[2 * pr + 1], ql[ks], kfh[pr][2], kfh[pr][3]);
            }
        }

        if (kt == qt) {
            const int r0 = wm * 16 + grp;
#pragma unroll
            for (int na = 0; na < 8; na++) {
                const int c0 = na * 8 + qid * 2;
                if (c0 > r0)     sacc[na][0] = -3.0e38f;
                if (c0 + 1 > r0) sacc[na][1] = -3.0e38f;
                if (c0 > r0 + 8)     sacc[na][2] = -3.0e38f;
                if (c0 + 1 > r0 + 8) sacc[na][3] = -3.0e38f;
            }
        }

        float rmax[2];
        rmax[0] = sacc[0][0]; rmax[1] = sacc[0][2];
#pragma unroll
        for (int na = 0; na < 8; na++) {
            rmax[0] = fmaxf(rmax[0], fmaxf(sacc[na][0], sacc[na][1]));
            rmax[1] = fmaxf(rmax[1], fmaxf(sacc[na][2], sacc[na][3]));
        }
#pragma unroll
        for (int d = 1; d <= 2; d <<= 1) {
            rmax[0] = fmaxf(rmax[0], __shfl_xor_sync(0xffffffffu, rmax[0], d));
            rmax[1] = fmaxf(rmax[1], __shfl_xor_sync(0xffffffffu, rmax[1], d));
        }
        float mnew[2], fsc[2];
#pragma unroll
        for (int i = 0; i < 2; i++) {
            mnew[i] = fmaxf(mrow[i], rmax[i]);
            fsc[i] = fast_exp2((mrow[i] - mnew[i]) * SC);
            mrow[i] = mnew[i];
        }

        float rsum[2] = {0.f, 0.f};
#pragma unroll
        for (int na = 0; na < 8; na++) {
            sacc[na][0] = fast_exp2((sacc[na][0] - mnew[0]) * SC);
            sacc[na][1] = fast_exp2((sacc[na][1] - mnew[0]) * SC);
            sacc[na][2] = fast_exp2((sacc[na][2] - mnew[1]) * SC);
            sacc[na][3] = fast_exp2((sacc[na][3] - mnew[1]) * SC);
            rsum[0] += sacc[na][0] + sacc[na][1];
            rsum[1] += sacc[na][2] + sacc[na][3];
        }
#pragma unroll
        for (int d = 1; d <= 2; d <<= 1) {
            rsum[0] += __shfl_xor_sync(0xffffffffu, rsum[0], d);
            rsum[1] += __shfl_xor_sync(0xffffffffu, rsum[1], d);
        }
        lrow[0] = lrow[0] * fsc[0] + rsum[0];
        lrow[1] = lrow[1] * fsc[1] + rsum[1];

        uint32_t ph[4][4], pl[4][4];
#pragma unroll
        for (int j = 0; j < 4; j++) {
#pragma unroll
            for (int u = 0; u < 2; u++) {
                const float* s4 = sacc[2 * j + u];
#pragma unroll
                for (int half = 0; half < 2; half++) {
                    float x = s4[half * 2 + 0], y = s4[half * 2 + 1];
                    __nv_bfloat162 hp = __float22bfloat162_rn(make_float2(x, y));
                    float2 hf2 = __bfloat1622float2(hp);
                    __nv_bfloat162 lp =
                        __float22bfloat162_rn(make_float2(x - hf2.x, y - hf2.y));
                    ph[j][u * 2 + half] = *reinterpret_cast<uint32_t*>(&hp);
                    pl[j][u * 2 + half] = *reinterpret_cast<uint32_t*>(&lp);
                }
            }
        }

#pragma unroll
        for (int na = 0; na < 8; na++) {
            oacc[na][0] *= fsc[0]; oacc[na][1] *= fsc[0];
            oacc[na][2] *= fsc[1]; oacc[na][3] *= fsc[1];
        }

        // ---- O += P V: j (K-chunk) outermost, hoist V frags, type-outermost
#pragma unroll
        for (int j = 0; j < 4; j++) {
            uint32_t vfh[4][4], vfl[4][4];
#pragma unroll
            for (int dp = 0; dp < 4; dp++) {
                const uint32_t va = stg + 2u * TILE_B +
                    (uint32_t)(j * 16 * 144 + dp * 32) + vadd;
                ldsm_x4_t(va, vfh[dp]);
                ldsm_x4_t(va + TILE_B, vfl[dp]);
            }
#pragma unroll
            for (int dp = 0; dp < 4; dp++) {
                mma_bf16(oacc[2 * dp],     ph[j], vfh[dp][0], vfh[dp][1]);
                mma_bf16(oacc[2 * dp + 1], ph[j], vfh[dp][2], vfh[dp][3]);
            }
#pragma unroll
            for (int dp = 0; dp < 4; dp++) {
                mma_bf16(oacc[2 * dp],     ph[j], vfl[dp][0], vfl[dp][1]);
                mma_bf16(oacc[2 * dp + 1], ph[j], vfl[dp][2], vfl[dp][3]);
            }
#pragma unroll
            for (int dp = 0; dp < 4; dp++) {
                mma_bf16(oacc[2 * dp],     pl[j], vfh[dp][0], vfh[dp][1]);
                mma_bf16(oacc[2 * dp + 1], pl[j], vfh[dp][2], vfh[dp][3]);
            }
        }
        __syncthreads();
    }

    // finalize: split O to bf16 hi/lo for the output-projection GEMM
    const float inv0 = 1.0f / lrow[0];
    const float inv1 = 1.0f / lrow[1];
    const int row0 = b * Tt + qt * 64 + wm * 16 + grp;
#pragma unroll
    for (int na = 0; na < 8; na++) {
        const int col = h * 64 + na * 8 + qid * 2;
#pragma unroll
        for (int half = 0; half < 2; half++) {
            float inv = half ? inv1 : inv0;
            float x = oacc[na][half * 2 + 0] * inv;
            float y = oacc[na][half * 2 + 1] * inv;
            __nv_bfloat162 hp = __float22bfloat162_rn(make_float2(x, y));
            float2 hf2 = __bfloat1622float2(hp);
            __nv_bfloat162 lp =
                __float22bfloat162_rn(make_float2(x - hf2.x, y - hf2.y));
            size_t off = (size_t)(row0 + half * 8) * HD + col;
            *reinterpret_cast<__nv_bfloat162*>(&g_AOh[off]) = hp;
            *reinterpret_cast<__nv_bfloat162*>(&g_AOl[off]) = lp;
        }
    }
}

// ---------------------------------------------------------------------------
// Launch
// ---------------------------------------------------------------------------
extern "C" void kernel_launch(void* const* d_in, const int* in_sizes, int n_in,
                              void* d_out, int out_size) {
    const float* q  = (const float*)d_in[0];
    const float* k  = (const float*)d_in[1];
    const float* v  = (const float*)d_in[2];
    const float* Wq = (const float*)d_in[3];
    const float* Wk = (const float*)d_in[4];
    const float* Wv = (const float*)d_in[5];
    const float* Wo = (const float*)d_in[6];
    const float* bo = (const float*)d_in[7];
    float* out = (float*)d_out;

    cudaFuncSetAttribute(qkv_gemm_kernel,
                         cudaFuncAttributeMaxDynamicSharedMemorySize, GEMM_SMEM_BYTES);
    cudaFuncSetAttribute(out_gemm_kernel,
                         cudaFuncAttributeMaxDynamicSharedMemorySize, GEMM_SMEM_BYTES);
    cudaFuncSetAttribute(flash2_kernel,
                         cudaFuncAttributeMaxDynamicSharedMemorySize, FLASH2_SMEM);

    pack_w_kernel<<<(Cc * HD) / 256, 256>>>(Wq, Wk, Wv, Wo);
    split_qkv_kernel<<<(MROWS * Cc) / (256 * 4), 256>>>(q, k, v);

    qkv_gemm_kernel<<<dim3(HD / 128, MROWS / 128, 3), 256, GEMM_SMEM_BYTES>>>();

    flash2_kernel<<<dim3(Tt / 64, Hh, Bb), 128, FLASH2_SMEM>>>();

    out_gemm_kernel<<<dim3(Cc / 128, MROWS / 128), 256, GEMM_SMEM_BYTES>>>(out, bo);
}